// round 15
// baseline (speedup 1.0000x reference)
#include <cuda_runtime.h>
#include <cuda_bf16.h>
#include <math.h>
#include <stdint.h>

// ---------------- problem constants ----------------
constexpr int BATCH = 2;
constexpr int T = 1024;
constexpr int CD = 1024;      // model dim
constexpr int H = 16;
constexpr int HD = 64;
constexpr int ROWS = BATCH * T;   // 2048
constexpr int BH = BATCH * H;     // 32
constexpr int NC = 16;
constexpr int CH = 64;

// GEMM tiling: CTA 128x128 (256 threads, 8 warps, 64x32 warp tiles),
// K-chunk 64, tiles pre-swizzled in gmem, 3-stage pipe
constexpr int TILE_BYTES = 128 * 64 * 2;                 // 16384
constexpr int STAGE_BYTES = 4 * TILE_BYTES;              // 65536
constexpr int SMEM_GEMM = 3 * STAGE_BYTES;               // 196608

// per-weight tile-buffer offsets (elements)
constexpr size_t OFF_QKV    = 0;
constexpr size_t OFF_SAPROJ = OFF_QKV    + (size_t)3072 * 1024;
constexpr size_t OFF_CAQ    = OFF_SAPROJ + (size_t)1024 * 1024;
constexpr size_t OFF_CAKV   = OFF_CAQ    + (size_t)1024 * 1024;
constexpr size_t OFF_CAPROJ = OFF_CAKV   + (size_t)2048 * 1024;
constexpr size_t OFF_FC     = OFF_CAPROJ + (size_t)1024 * 1024;
constexpr size_t OFF_FCP    = OFF_FC     + (size_t)4096 * 1024;
constexpr size_t WTOTAL     = OFF_FCP    + (size_t)1024 * 4096;   // 16M elements

// flattened conversion grid: block ranges per job
constexpr int BLK_QKV    = 768;
constexpr int BLK_SAPROJ = 256;
constexpr int BLK_CAQ    = 256;
constexpr int BLK_CAKV   = 512;
constexpr int BLK_CAPROJ = 256;
constexpr int BLK_FC     = 1024;
constexpr int BLK_FCP    = 1024;
constexpr int BLK_MEM    = 1024;
constexpr int BLK_LN1    = 2048;
constexpr int B0 = 0;
constexpr int B1 = B0 + BLK_QKV;
constexpr int B2 = B1 + BLK_SAPROJ;
constexpr int B3 = B2 + BLK_CAQ;
constexpr int B4 = B3 + BLK_CAKV;
constexpr int B5 = B4 + BLK_CAPROJ;
constexpr int B6 = B5 + BLK_FC;
constexpr int B7 = B6 + BLK_FCP;
constexpr int B8 = B7 + BLK_MEM;
constexpr int BTOT = B8 + BLK_LN1;  // 7168

// ---------------- device scratch -------------------
__device__ float g_h[ROWS * 4096];
__device__ float g_qkv[ROWS * 3072];
__device__ float g_Qf[BH * T * HD];
__device__ float g_Qr[BH * T * HD];
__device__ float g_Kf[BH * T * HD];
__device__ float g_Kr[BH * T * HD];
__device__ float g_V [BH * T * HD];
__device__ float g_Z [BH * HD];
__device__ float g_Zpart[BH * NC * HD];
__device__ float g_Schunk[BH * NC * HD * HD];
__device__ float g_Stot[BH * HD * HD];
__device__ float g_cos[T * HD];
__device__ float g_sin[T * HD];
// tiled + swizzled bf16 operand buffers
__device__ __align__(1024) __nv_bfloat16 g_Ah[ROWS * 4096];
__device__ __align__(1024) __nv_bfloat16 g_Al[ROWS * 4096];
__device__ __align__(1024) __nv_bfloat16 g_Ah2[ROWS * 4096];
__device__ __align__(1024) __nv_bfloat16 g_Al2[ROWS * 4096];
__device__ __align__(1024) __nv_bfloat16 g_Bh[WTOTAL];
__device__ __align__(1024) __nv_bfloat16 g_Bl[WTOTAL];

// ---------------- small helpers --------------------
__device__ __forceinline__ float gelu_tanh(float x) {
    const float c = 0.7978845608028654f;
    float t = tanhf(c * (x + 0.044715f * x * x * x));
    return 0.5f * x * (1.0f + t);
}
__device__ __forceinline__ float featmap(float x) {
    return x > 0.0f ? x + 1.0f : __expf(x);
}
__device__ __forceinline__ uint32_t smem_u32(const void* p) {
    uint32_t a;
    asm("{ .reg .u64 t; cvta.to.shared.u64 t, %1; cvt.u32.u64 %0, t; }" : "=r"(a) : "l"(p));
    return a;
}
__device__ __forceinline__ uint32_t swz128(uint32_t off) {
    return off ^ ((off >> 3) & 0x70);
}
__device__ __forceinline__ void split8(const float* x, uint4& uh, uint4& ul) {
    __align__(16) __nv_bfloat16 h[8];
    __align__(16) __nv_bfloat16 l[8];
    #pragma unroll
    for (int i = 0; i < 8; i++) {
        __nv_bfloat16 hh = __float2bfloat16(x[i]);
        h[i] = hh;
        l[i] = __float2bfloat16(x[i] - __bfloat162float(hh));
    }
    uh = *(const uint4*)h;
    ul = *(const uint4*)l;
}
__device__ __forceinline__ void split2(float a, float b, uint32_t& hp, uint32_t& lp) {
    __nv_bfloat16 h0 = __float2bfloat16(a);
    __nv_bfloat16 h1 = __float2bfloat16(b);
    __nv_bfloat16 l0 = __float2bfloat16(a - __bfloat162float(h0));
    __nv_bfloat16 l1 = __float2bfloat16(b - __bfloat162float(h1));
    __nv_bfloat162 hv = {h0, h1}, lv = {l0, l1};
    hp = *(uint32_t*)&hv;
    lp = *(uint32_t*)&lv;
}

// ---------------- cp.async / ldmatrix / mma --------
__device__ __forceinline__ void cp16(uint32_t dst, const void* src) {
    asm volatile("cp.async.cg.shared.global [%0], [%1], 16;" :: "r"(dst), "l"(src));
}
__device__ __forceinline__ void cp_commit() {
    asm volatile("cp.async.commit_group;");
}
__device__ __forceinline__ void ldmx4(uint32_t& r0, uint32_t& r1, uint32_t& r2, uint32_t& r3, uint32_t addr) {
    asm volatile("ldmatrix.sync.aligned.m8n8.x4.shared.b16 {%0,%1,%2,%3}, [%4];"
                 : "=r"(r0), "=r"(r1), "=r"(r2), "=r"(r3) : "r"(addr));
}
__device__ __forceinline__ void mma16816(float* d, uint32_t a0, uint32_t a1, uint32_t a2, uint32_t a3,
                                         uint32_t b0, uint32_t b1) {
    asm volatile(
        "mma.sync.aligned.m16n8k16.row.col.f32.bf16.bf16.f32 "
        "{%0,%1,%2,%3}, {%4,%5,%6,%7}, {%8,%9}, {%0,%1,%2,%3};"
        : "+f"(d[0]), "+f"(d[1]), "+f"(d[2]), "+f"(d[3])
        : "r"(a0), "r"(a1), "r"(a2), "r"(a3), "r"(b0), "r"(b1));
}

// ---------------- RoPE tables ----------------------
__global__ void rope_init_kernel() {
    int t = blockIdx.x;
    int d = threadIdx.x;
    int i = d & 31;
    double inv = pow(10000.0, -(double)i / 32.0);
    double ang = (double)t * inv;
    g_cos[t * HD + d] = (float)cos(ang);
    g_sin[t * HD + d] = (float)sin(ang);
}

// ---------------- conversion bodies (device) --------
__device__ __forceinline__ void convW_block(
    const float* __restrict__ W, int Nn, int K,
    __nv_bfloat16* __restrict__ dsth, __nv_bfloat16* __restrict__ dstl,
    int kb, int nb, float (*smw)[65])
{
    int tid = threadIdx.x;
    #pragma unroll
    for (int i = 0; i < 4; i++) {
        int idx = tid * 4 + i;
        int kl = idx >> 4, f4 = idx & 15;
        float4 v = *(const float4*)(W + (size_t)(kb + kl) * Nn + nb + f4 * 4);
        smw[kl][f4 * 4 + 0] = v.x;
        smw[kl][f4 * 4 + 1] = v.y;
        smw[kl][f4 * 4 + 2] = v.z;
        smw[kl][f4 * 4 + 3] = v.w;
    }
    __syncthreads();
    int nkc = K >> 6, kc = kb >> 6;
    #pragma unroll
    for (int i = 0; i < 2; i++) {
        int cid = tid * 2 + i;
        int nl64 = cid >> 3, k8 = (cid & 7) * 8;
        int n = nb + nl64;
        int nt = n >> 7, nl = n & 127;
        float vals[8];
        #pragma unroll
        for (int j = 0; j < 8; j++) vals[j] = smw[k8 + j][nl64];
        uint4 uh, ul;
        split8(vals, uh, ul);
        uint32_t sw = swz128((uint32_t)(nl * 128 + k8 * 2));
        size_t tb = ((size_t)nt * nkc + kc) * TILE_BYTES + sw;
        *(uint4*)((char*)dsth + tb) = uh;
        *(uint4*)((char*)dstl + tb) = ul;
    }
}

__device__ __forceinline__ void convA_block(
    const float* __restrict__ in, int K,
    __nv_bfloat16* __restrict__ dsth, __nv_bfloat16* __restrict__ dstl,
    int blk)
{
    size_t gid = ((size_t)blk * 256 + threadIdx.x) * 8;
    int m = (int)(gid / K);
    int n0 = (int)(gid % K);
    float vals[8];
    float4 a = *(const float4*)(in + gid);
    float4 b = *(const float4*)(in + gid + 4);
    vals[0] = a.x; vals[1] = a.y; vals[2] = a.z; vals[3] = a.w;
    vals[4] = b.x; vals[5] = b.y; vals[6] = b.z; vals[7] = b.w;
    uint4 uh, ul;
    split8(vals, uh, ul);
    int nkc = K >> 6;
    int mt = m >> 7, rl = m & 127, kc = n0 >> 6, kl = n0 & 63;
    uint32_t sw = swz128((uint32_t)(rl * 128 + kl * 2));
    size_t tb = ((size_t)mt * nkc + kc) * TILE_BYTES + sw;
    *(uint4*)((char*)dsth + tb) = uh;
    *(uint4*)((char*)dstl + tb) = ul;
}

__device__ __forceinline__ void ln_block(
    const float* __restrict__ in, const float* __restrict__ gam,
    const float* __restrict__ bet, int r, float* row)
{
    int tid = threadIdx.x;
    float* red1 = row + CD;
    float* red2 = row + CD + 8;
    float* mv   = row + CD + 16;
    float4 v = ((const float4*)(in + (size_t)r * CD))[tid];
    ((float4*)row)[tid] = v;
    float s1 = v.x + v.y + v.z + v.w;
    float s2 = v.x * v.x + v.y * v.y + v.z * v.z + v.w * v.w;
    #pragma unroll
    for (int o = 16; o > 0; o >>= 1) {
        s1 += __shfl_xor_sync(0xFFFFFFFFu, s1, o);
        s2 += __shfl_xor_sync(0xFFFFFFFFu, s2, o);
    }
    if ((tid & 31) == 0) { red1[tid >> 5] = s1; red2[tid >> 5] = s2; }
    __syncthreads();
    if (tid == 0) {
        float a = 0.f, b = 0.f;
        #pragma unroll
        for (int i = 0; i < 8; i++) { a += red1[i]; b += red2[i]; }
        float mean = a * (1.0f / CD);
        mv[0] = mean;
        mv[1] = rsqrtf(b * (1.0f / CD) - mean * mean + 1e-5f);
    }
    __syncthreads();
    float mean = mv[0], rstd = mv[1];
    if (tid < 128) {
        int n0 = tid * 8;
        float vals[8];
        #pragma unroll
        for (int i = 0; i < 8; i++)
            vals[i] = (row[n0 + i] - mean) * rstd * gam[n0 + i] + bet[n0 + i];
        uint4 uh, ul;
        split8(vals, uh, ul);
        int mt = r >> 7, rl = r & 127, kc = n0 >> 6, kl = n0 & 63;
        uint32_t sw = swz128((uint32_t)(rl * 128 + kl * 2));
        size_t tb = ((size_t)(mt * 16 + kc)) * TILE_BYTES + sw;
        *(uint4*)((char*)g_Ah + tb) = uh;
        *(uint4*)((char*)g_Al + tb) = ul;
    }
}

// ---------------- standalone LN (for ln2/ln3) ------
__global__ void __launch_bounds__(256) ln_tiled_kernel(
    const float* __restrict__ in, const float* __restrict__ gam,
    const float* __restrict__ bet)
{
    __shared__ float row[CD + 32];
    ln_block(in, gam, bet, blockIdx.x, row);
}

// ---------------- ALL conversions + ln1 in one launch ----
__global__ void __launch_bounds__(256) convAll_kernel(
    const float* __restrict__ qkv_w, const float* __restrict__ saproj_w,
    const float* __restrict__ caq_w, const float* __restrict__ cakv_w,
    const float* __restrict__ caproj_w, const float* __restrict__ fc_w,
    const float* __restrict__ fcp_w, const float* __restrict__ mem,
    const float* __restrict__ x, const float* __restrict__ ln1_g,
    const float* __restrict__ ln1_b,
    __nv_bfloat16* __restrict__ Bh, __nv_bfloat16* __restrict__ Bl,
    __nv_bfloat16* __restrict__ Ah2, __nv_bfloat16* __restrict__ Al2)
{
    __shared__ float smw[64][65];
    int blk = blockIdx.x;
    if (blk < B1) {
        int lb = blk - B0;
        convW_block(qkv_w, 3072, 1024, Bh + OFF_QKV, Bl + OFF_QKV,
                    (lb % 16) * 64, (lb / 16) * 64, smw);
    } else if (blk < B2) {
        int lb = blk - B1;
        convW_block(saproj_w, 1024, 1024, Bh + OFF_SAPROJ, Bl + OFF_SAPROJ,
                    (lb % 16) * 64, (lb / 16) * 64, smw);
    } else if (blk < B3) {
        int lb = blk - B2;
        convW_block(caq_w, 1024, 1024, Bh + OFF_CAQ, Bl + OFF_CAQ,
                    (lb % 16) * 64, (lb / 16) * 64, smw);
    } else if (blk < B4) {
        int lb = blk - B3;
        convW_block(cakv_w, 2048, 1024, Bh + OFF_CAKV, Bl + OFF_CAKV,
                    (lb % 16) * 64, (lb / 16) * 64, smw);
    } else if (blk < B5) {
        int lb = blk - B4;
        convW_block(caproj_w, 1024, 1024, Bh + OFF_CAPROJ, Bl + OFF_CAPROJ,
                    (lb % 16) * 64, (lb / 16) * 64, smw);
    } else if (blk < B6) {
        int lb = blk - B5;
        convW_block(fc_w, 4096, 1024, Bh + OFF_FC, Bl + OFF_FC,
                    (lb % 16) * 64, (lb / 16) * 64, smw);
    } else if (blk < B7) {
        int lb = blk - B6;
        convW_block(fcp_w, 1024, 4096, Bh + OFF_FCP, Bl + OFF_FCP,
                    (lb % 64) * 64, (lb / 64) * 64, smw);
    } else if (blk < B8) {
        convA_block(mem, 1024, Ah2, Al2, blk - B7);
    } else {
        ln_block(x, ln1_g, ln1_b, blk - B8, &smw[0][0]);
    }
}

// ---------------- mma.sync bf16x3 GEMM (8 warps) ----
// epi: 0 = +bias; 1 = gelu(+bias); 2 = +bias + resid;
//      3 = gelu(+bias) -> split-tiled bf16 into outAh/outAl
//      4 = qkv fused featuremap (cols: 0..1023 q, 1024..2047 k, 2048.. v)
//      5 = q-only fused featuremap
//      6 = kv fused featuremap (cols: 0..1023 k, 1024.. v)
__global__ void __launch_bounds__(256, 1) gemm_mma_kernel(
    const __nv_bfloat16* __restrict__ Ah, const __nv_bfloat16* __restrict__ Al,
    const __nv_bfloat16* __restrict__ Bh, const __nv_bfloat16* __restrict__ Bl,
    const float* __restrict__ bias, const float* __restrict__ resid,
    float* __restrict__ out, __nv_bfloat16* __restrict__ outAh,
    __nv_bfloat16* __restrict__ outAl, int Nn, int K, int epi)
{
    extern __shared__ __align__(1024) char smg[];
    uint32_t sb = smem_u32(smg);
    int tid = threadIdx.x;
    int w = tid >> 5, l = tid & 31;
    int wm = w & 1, wn = w >> 1;           // warp tile: 64x32 at (wm*64, wn*32)
    int bx = blockIdx.x, by = blockIdx.y;
    int nkc = K >> 6;

    auto prefetch = [&](int c, int s) {
        uint32_t st = sb + s * STAGE_BYTES;
        const char* pah = (const char*)Ah + ((size_t)by * nkc + c) * TILE_BYTES;
        const char* pal = (const char*)Al + ((size_t)by * nkc + c) * TILE_BYTES;
        const char* pbh = (const char*)Bh + ((size_t)bx * nkc + c) * TILE_BYTES;
        const char* pbl = (const char*)Bl + ((size_t)bx * nkc + c) * TILE_BYTES;
        #pragma unroll
        for (int r = 0; r < 4; r++) {
            uint32_t o = (uint32_t)(r * 256 + tid) * 16;
            cp16(st + o,                  pah + o);
            cp16(st + TILE_BYTES + o,     pal + o);
            cp16(st + 2 * TILE_BYTES + o, pbh + o);
            cp16(st + 3 * TILE_BYTES + o, pbl + o);
        }
        cp_commit();
    };

    float acc[4][4][4];
    #pragma unroll
    for (int i = 0; i < 4; i++)
        #pragma unroll
        for (int j = 0; j < 4; j++)
            #pragma unroll
            for (int q = 0; q < 4; q++) acc[i][j][q] = 0.f;

    prefetch(0, 0);
    if (nkc > 1) prefetch(1, 1);

    int seg = l >> 3, l7 = l & 7;
    int arow = wm * 64 + (seg & 1) * 8 + l7;
    int akb  = (seg >> 1) * 16;
    int brow = wn * 32 + (seg >> 1) * 8 + l7;
    int bkb  = (seg & 1) * 16;

    for (int c = 0; c < nkc; c++) {
        int s = c % 3;
        if (c + 1 < nkc) asm volatile("cp.async.wait_group 1;");
        else             asm volatile("cp.async.wait_group 0;");
        __syncthreads();
        if (c + 2 < nkc) prefetch(c + 2, (c + 2) % 3);
        uint32_t st = sb + s * STAGE_BYTES;
        #pragma unroll
        for (int ks = 0; ks < 4; ks++) {
            uint32_t bh_[4][2], bl_[4][2];
            #pragma unroll
            for (int jp = 0; jp < 2; jp++) {
                uint32_t off = swz128((uint32_t)((brow + jp * 16) * 128 + ks * 32 + bkb));
                ldmx4(bh_[2 * jp][0], bh_[2 * jp][1], bh_[2 * jp + 1][0], bh_[2 * jp + 1][1],
                      st + 2 * TILE_BYTES + off);
                ldmx4(bl_[2 * jp][0], bl_[2 * jp][1], bl_[2 * jp + 1][0], bl_[2 * jp + 1][1],
                      st + 3 * TILE_BYTES + off);
            }
            #pragma unroll
            for (int i = 0; i < 4; i++) {
                uint32_t off = swz128((uint32_t)((arow + i * 16) * 128 + ks * 32 + akb));
                uint32_t a0, a1, a2, a3, c0, c1, c2, c3;
                ldmx4(a0, a1, a2, a3, st + off);
                ldmx4(c0, c1, c2, c3, st + TILE_BYTES + off);
                #pragma unroll
                for (int j = 0; j < 4; j++) {
                    mma16816(acc[i][j], a0, a1, a2, a3, bh_[j][0], bh_[j][1]);
                    mma16816(acc[i][j], a0, a1, a2, a3, bl_[j][0], bl_[j][1]);
                    mma16816(acc[i][j], c0, c1, c2, c3, bh_[j][0], bh_[j][1]);
                }
            }
        }
        __syncthreads();
    }

    int g = l >> 2, tq = l & 3;

    if (epi >= 4) {
        // fused featuremap epilogue: stage fp32 tile in smem (stride 132),
        // then apply elu+1 / RoPE with in-tile partner and scatter head-major.
        float* ftile = (float*)smg;
        #pragma unroll
        for (int i = 0; i < 4; i++) {
            #pragma unroll
            for (int j = 0; j < 4; j++) {
                int lr = wm * 64 + i * 16 + g;
                int lc = wn * 32 + j * 8 + tq * 2;
                float2 bb2 = *(const float2*)(bias + bx * 128 + lc);
                ftile[lr * 132 + lc]           = acc[i][j][0] + bb2.x;
                ftile[lr * 132 + lc + 1]       = acc[i][j][1] + bb2.y;
                ftile[(lr + 8) * 132 + lc]     = acc[i][j][2] + bb2.x;
                ftile[(lr + 8) * 132 + lc + 1] = acc[i][j][3] + bb2.y;
            }
        }
        __syncthreads();
        int lr = tid >> 1, c0 = (tid & 1) * 64;
        int m = by * 128 + lr;
        int bb = m >> 10, tt = m & 1023;
        int ng = bx * 128 + c0;
        int type, ct;
        if (epi == 4)      { type = ng >> 10;       ct = ng & 1023; }
        else if (epi == 5) { type = 0;              ct = ng; }
        else               { type = 1 + (ng >> 10); ct = ng & 1023; }
        int hh = ct >> 6;
        size_t o = ((size_t)(bb * H + hh) * T + tt) * HD;
        const float* frow = ftile + lr * 132 + c0;
        if (type == 2) {
            #pragma unroll 4
            for (int d = 0; d < HD; d++) g_V[o + d] = frow[d];
        } else {
            float* Ff = (type == 0) ? g_Qf : g_Kf;
            float* Fr = (type == 0) ? g_Qr : g_Kr;
            for (int d = 0; d < HD; d++) {
                float xv = featmap(frow[d]);
                float xp = featmap(frow[d ^ 32]);
                float rot = (d < 32) ? -xp : xp;
                float cs = g_cos[tt * HD + d], sn = g_sin[tt * HD + d];
                Ff[o + d] = xv;
                Fr[o + d] = xv * cs + rot * sn;
            }
        }
        return;
    }

    // standard epilogue
    int mBase = by * 128 + wm * 64;
    int nBase = bx * 128 + wn * 32;
    int nkcOut = Nn >> 6;
    #pragma unroll
    for (int i = 0; i < 4; i++) {
        #pragma unroll
        for (int j = 0; j < 4; j++) {
            int m0 = mBase + i * 16 + g;
            int n0 = nBase + j * 8 + tq * 2;
            float2 bb = *(const float2*)(bias + n0);
            float v0 = acc[i][j][0] + bb.x, v1 = acc[i][j][1] + bb.y;
            float v2 = acc[i][j][2] + bb.x, v3 = acc[i][j][3] + bb.y;
            if (epi == 1 || epi == 3) {
                v0 = gelu_tanh(v0); v1 = gelu_tanh(v1);
                v2 = gelu_tanh(v2); v3 = gelu_tanh(v3);
            } else if (epi == 2) {
                float2 r0 = *(const float2*)(resid + (size_t)m0 * Nn + n0);
                float2 r1 = *(const float2*)(resid + (size_t)(m0 + 8) * Nn + n0);
                v0 += r0.x; v1 += r0.y; v2 += r1.x; v3 += r1.y;
            }
            if (epi == 3) {
                int kc = n0 >> 6, kl = n0 & 63;
                uint32_t sw = swz128((uint32_t)((m0 & 127) * 128 + kl * 2));
                size_t tb0 = ((size_t)((m0 >> 7) * nkcOut + kc)) * TILE_BYTES + sw;
                uint32_t sw1 = swz128((uint32_t)(((m0 + 8) & 127) * 128 + kl * 2));
                size_t tb1 = ((size_t)(((m0 + 8) >> 7) * nkcOut + kc)) * TILE_BYTES + sw1;
                uint32_t hp, lp;
                split2(v0, v1, hp, lp);
                *(uint32_t*)((char*)outAh + tb0) = hp;
                *(uint32_t*)((char*)outAl + tb0) = lp;
                split2(v2, v3, hp, lp);
                *(uint32_t*)((char*)outAh + tb1) = hp;
                *(uint32_t*)((char*)outAl + tb1) = lp;
            } else {
                float2 o0 = {v0, v1}, o1 = {v2, v3};
                *(float2*)(out + (size_t)m0 * Nn + n0) = o0;
                *(float2*)(out + (size_t)(m0 + 8) * Nn + n0) = o1;
            }
        }
    }
}

// ---------------- per-chunk Kr (outer) V sums + Kf chunk partials ----
__global__ void __launch_bounds__(256) chunksum_kernel() {
    int bh = blockIdx.x / NC;
    int c  = blockIdx.x % NC;
    int tid = threadIdx.x;
    __shared__ float Ks[CH][HD];
    __shared__ float Vs[CH][HD];
    __shared__ float zred[4][HD];
    size_t gbase = ((size_t)bh * T + c * CH) * HD;
    for (int idx = tid; idx < CH * HD; idx += 256) {
        Ks[idx >> 6][idx & 63] = g_Kr[gbase + idx];
        Vs[idx >> 6][idx & 63] = g_V [gbase + idx];
    }
    {
        int j = tid & 63, rr = tid >> 6;
        const float* kf = g_Kf + gbase;
        float zs = 0.f;
        for (int t = rr; t < CH; t += 4) zs += kf[(size_t)t * HD + j];
        zred[rr][j] = zs;
    }
    __syncthreads();
    if (tid < 64)
        g_Zpart[(bh * NC + c) * 64 + tid] =
            zred[0][tid] + zred[1][tid] + zred[2][tid] + zred[3][tid];

    int j = tid & 63, i0 = tid >> 6;
    float acc[16];
    #pragma unroll
    for (int k = 0; k < 16; k++) acc[k] = 0.f;
    for (int t = 0; t < CH; t++) {
        float vv = Vs[t][j];
        #pragma unroll
        for (int k = 0; k < 16; k++) acc[k] = fmaf(Ks[t][i0 + 4 * k], vv, acc[k]);
    }
    float* out = g_Schunk + ((size_t)bh * NC + c) * (HD * HD);
    #pragma unroll
    for (int k = 0; k < 16; k++) out[(i0 + 4 * k) * HD + j] = acc[k];
}

// ---------------- exclusive prefix over chunks (+ Z reduce) ----
__global__ void __launch_bounds__(256) prefix_kernel() {
    int bh = blockIdx.x;
    int e = blockIdx.y * 256 + threadIdx.x;
    if (blockIdx.y == 0 && threadIdx.x < 64) {
        int d = threadIdx.x;
        float s = 0.f;
        for (int i = 0; i < NC; i++) s += g_Zpart[(bh * NC + i) * 64 + d];
        g_Z[bh * HD + d] = s;
    }
    float run = 0.f;
    for (int c = 0; c < NC; c++) {
        size_t idx = ((size_t)bh * NC + c) * (HD * HD) + e;
        float tmp = g_Schunk[idx];
        g_Schunk[idx] = run;
        run += tmp;
    }
    g_Stot[(size_t)bh * (HD * HD) + e] = run;
}

// ---------------- write y (split-tiled bf16, K=1024 layout) ----
__device__ __forceinline__ void write_y_tiled(int row, int hh, int j, float a) {
    int rl = row & 127, mt = row >> 7;
    size_t tb = ((size_t)(mt * 16 + hh)) * TILE_BYTES + swz128((uint32_t)(rl * 128 + j * 2));
    __nv_bfloat16 hbf = __float2bfloat16(a);
    __nv_bfloat16 lbf = __float2bfloat16(a - __bfloat162float(hbf));
    *(__nv_bfloat16*)((char*)g_Ah + tb) = hbf;
    *(__nv_bfloat16*)((char*)g_Al + tb) = lbf;
}

// ---------------- causal chunked attention ----------
constexpr int SMEM_CAUSAL = (5 * HD * HD + 2 * HD) * 4;
__global__ void __launch_bounds__(256) causal_attn_kernel() {
    extern __shared__ float smc[];
    float* Qrs = smc;
    float* Krs = smc + 4096;
    float* Vs  = smc + 8192;
    float* Sps = smc + 12288;
    float* att = smc + 16384;
    float* den = smc + 20480;
    float* Zs  = smc + 20544;

    int bh = blockIdx.x / NC;
    int c  = blockIdx.x % NC;
    int b = bh / H, hh = bh % H;
    int tid = threadIdx.x;
    size_t qbase = ((size_t)bh * T + c * CH) * HD;

    for (int idx = tid; idx < 4096; idx += 256) {
        Qrs[idx] = g_Qr[qbase + idx];
        Krs[idx] = g_Kr[qbase + idx];
        Vs[idx]  = g_V [qbase + idx];
        Sps[idx] = g_Schunk[((size_t)bh * NC + c) * 4096 + idx];
    }
    if (tid < HD) Zs[tid] = g_Z[bh * HD + tid];
    __syncthreads();

    if (tid < CH) {
        const float* qf = g_Qf + qbase + (size_t)tid * HD;
        float s = 0.f;
        #pragma unroll
        for (int d = 0; d < HD; d++) s = fmaf(qf[d], Zs[d], s);
        den[tid] = s;
    }
    for (int e = tid; e < 4096; e += 256) {
        int t = e >> 6, s = e & 63;
        float v = 0.f;
        if (s <= t) {
            #pragma unroll
            for (int d = 0; d < HD; d++) v = fmaf(Qrs[t * HD + d], Krs[s * HD + d], v);
        }
        att[e] = v;
    }
    __syncthreads();

    int j = tid & 63, i0 = tid >> 6;
    #pragma unroll
    for (int k = 0; k < 16; k++) {
        int t = i0 + 4 * k;
        float a = 0.f;
        #pragma unroll
        for (int d = 0; d < HD; d++) a = fmaf(Qrs[t * HD + d], Sps[d * HD + j], a);
        #pragma unroll
        for (int s = 0; s < CH; s++) a = fmaf(att[t * HD + s], Vs[s * HD + j], a);
        a /= den[t];
        write_y_tiled(b * T + c * CH + t, hh, j, a);
    }
}

// ---------------- cross attention -------------------
__global__ void __launch_bounds__(256) cross_attn_kernel() {
    __shared__ float Qrs[4096], St[4096], den[CH], Zs[HD];
    int bh = blockIdx.x / NC;
    int c  = blockIdx.x % NC;
    int b = bh / H, hh = bh % H;
    int tid = threadIdx.x;
    size_t qbase = ((size_t)bh * T + c * CH) * HD;

    for (int idx = tid; idx < 4096; idx += 256) {
        Qrs[idx] = g_Qr[qbase + idx];
        St[idx]  = g_Stot[(size_t)bh * 4096 + idx];
    }
    if (tid < HD) Zs[tid] = g_Z[bh * HD + tid];
    __syncthreads();
    if (tid < CH) {
        const float* qf = g_Qf + qbase + (size_t)tid * HD;
        float s = 0.f;
        #pragma unroll
        for (int d = 0; d < HD; d++) s = fmaf(qf[d], Zs[d], s);
        den[tid] = s;
    }
    __syncthreads();

    int j = tid & 63, i0 = tid >> 6;
    #pragma unroll
    for (int k = 0; k < 16; k++) {
        int t = i0 + 4 * k;
        float a = 0.f;
        #pragma unroll
        for (int d = 0; d < HD; d++) a = fmaf(Qrs[t * HD + d], St[d * HD + j], a);
        a /= den[t];
        write_y_tiled(b * T + c * CH + t, hh, j, a);
    }
}

// ---------------- host ------------------------------
static void launch_gemm(const __nv_bfloat16* Ah, const __nv_bfloat16* Al,
                        const __nv_bfloat16* Bh, const __nv_bfloat16* Bl,
                        const float* bias, const float* resid, float* out,
                        __nv_bfloat16* oAh, __nv_bfloat16* oAl,
                        int Nn, int K, int epi)
{
    dim3 grid(Nn / 128, ROWS / 128);
    gemm_mma_kernel<<<grid, 256, SMEM_GEMM>>>(Ah, Al, Bh, Bl, bias, resid, out, oAh, oAl, Nn, K, epi);
}

extern "C" void kernel_launch(void* const* d_in, const int* in_sizes, int n_in,
                              void* d_out, int out_size)
{
    const float* x        = (const float*)d_in[0];
    const float* memory   = (const float*)d_in[1];
    const float* ln1_g    = (const float*)d_in[2];
    const float* ln1_b    = (const float*)d_in[3];
    const float* sa_qkv_w = (const float*)d_in[4];
    const float* sa_qkv_b = (const float*)d_in[5];
    const float* sa_proj_w= (const float*)d_in[6];
    const float* sa_proj_b= (const float*)d_in[7];
    const float* ln2_g    = (const float*)d_in[8];
    const float* ln2_b    = (const float*)d_in[9];
    const float* ca_q_w   = (const float*)d_in[10];
    const float* ca_q_b   = (const float*)d_in[11];
    const float* ca_kv_w  = (const float*)d_in[12];
    const float* ca_kv_b  = (const float*)d_in[13];
    const float* ca_proj_w= (const float*)d_in[14];
    const float* ca_proj_b= (const float*)d_in[15];
    const float* ln3_g    = (const float*)d_in[16];
    const float* ln3_b    = (const float*)d_in[17];
    const float* fc_w     = (const float*)d_in[18];
    const float* fc_b     = (const float*)d_in[19];
    const float* fcp_w    = (const float*)d_in[20];
    const float* fcp_b    = (const float*)d_in[21];
    float* out = (float*)d_out;

    cudaFuncSetAttribute(gemm_mma_kernel,
                         cudaFuncAttributeMaxDynamicSharedMemorySize, SMEM_GEMM);
    cudaFuncSetAttribute(causal_attn_kernel,
                         cudaFuncAttributeMaxDynamicSharedMemorySize, SMEM_CAUSAL);

    float *hbuf, *qkvbuf;
    __nv_bfloat16 *Ah, *Al, *Ah2, *Al2, *Bh, *Bl;
    cudaGetSymbolAddress((void**)&hbuf,   g_h);
    cudaGetSymbolAddress((void**)&qkvbuf, g_qkv);
    cudaGetSymbolAddress((void**)&Ah, g_Ah);
    cudaGetSymbolAddress((void**)&Al, g_Al);
    cudaGetSymbolAddress((void**)&Ah2, g_Ah2);
    cudaGetSymbolAddress((void**)&Al2, g_Al2);
    cudaGetSymbolAddress((void**)&Bh, g_Bh);
    cudaGetSymbolAddress((void**)&Bl, g_Bl);

    rope_init_kernel<<<T, HD>>>();

    // ---- ALL conversions + ln1 in a single launch ----
    convAll_kernel<<<BTOT, 256>>>(sa_qkv_w, sa_proj_w, ca_q_w, ca_kv_w,
                                  ca_proj_w, fc_w, fcp_w, memory,
                                  x, ln1_g, ln1_b, Bh, Bl, Ah2, Al2);

    // ---- self attention ----
    launch_gemm(Ah, Al, Bh + OFF_QKV, Bl + OFF_QKV, sa_qkv_b, nullptr, nullptr, nullptr, nullptr, 3072, 1024, 4);
    chunksum_kernel<<<BH * NC, 256>>>();
    prefix_kernel<<<dim3(BH, 16), 256>>>();
    causal_attn_kernel<<<BH * NC, 256, SMEM_CAUSAL>>>();   // writes y tiles -> Ah/Al
    launch_gemm(Ah, Al, Bh + OFF_SAPROJ, Bl + OFF_SAPROJ, sa_proj_b, x, out, nullptr, nullptr, 1024, 1024, 2);

    // ---- cross attention ----
    ln_tiled_kernel<<<ROWS, 256>>>(out, ln2_g, ln2_b);
    launch_gemm(Ah, Al, Bh + OFF_CAQ, Bl + OFF_CAQ, ca_q_b, nullptr, nullptr, nullptr, nullptr, 1024, 1024, 5);
    launch_gemm(Ah2, Al2, Bh + OFF_CAKV, Bl + OFF_CAKV, ca_kv_b, nullptr, nullptr, nullptr, nullptr, 2048, 1024, 6);
    chunksum_kernel<<<BH * NC, 256>>>();
    prefix_kernel<<<dim3(BH, 16), 256>>>();
    cross_attn_kernel<<<BH * NC, 256>>>();                 // writes y tiles -> Ah/Al
    launch_gemm(Ah, Al, Bh + OFF_CAPROJ, Bl + OFF_CAPROJ, ca_proj_b, out, out, nullptr, nullptr, 1024, 1024, 2);

    // ---- MLP ----
    ln_tiled_kernel<<<ROWS, 256>>>(out, ln3_g, ln3_b);
    launch_gemm(Ah, Al, Bh + OFF_FC, Bl + OFF_FC, fc_b, nullptr, nullptr, Ah2, Al2, 4096, 1024, 3);
    launch_gemm(Ah2, Al2, Bh + OFF_FCP, Bl + OFF_FCP, fcp_b, out, out, nullptr, nullptr, 1024, 4096, 2);
}

// round 16
// speedup vs baseline: 1.2732x; 1.2732x over previous
#include <cuda_runtime.h>
#include <cuda_bf16.h>
#include <math.h>
#include <stdint.h>

// ---------------- problem constants ----------------
constexpr int BATCH = 2;
constexpr int T = 1024;
constexpr int CD = 1024;      // model dim
constexpr int H = 16;
constexpr int HD = 64;
constexpr int ROWS = BATCH * T;   // 2048
constexpr int BH = BATCH * H;     // 32
constexpr int NC = 16;
constexpr int CH = 64;

// GEMM tiling: CTA 128x128 (256 threads, 8 warps, 64x32 warp tiles),
// K-chunk 64, tiles pre-swizzled in gmem, 3-stage pipe
constexpr int TILE_BYTES = 128 * 64 * 2;                 // 16384
constexpr int STAGE_BYTES = 4 * TILE_BYTES;              // 65536
constexpr int SMEM_GEMM = 3 * STAGE_BYTES;               // 196608

// per-weight tile-buffer offsets (elements)
constexpr size_t OFF_QKV    = 0;
constexpr size_t OFF_SAPROJ = OFF_QKV    + (size_t)3072 * 1024;
constexpr size_t OFF_CAQ    = OFF_SAPROJ + (size_t)1024 * 1024;
constexpr size_t OFF_CAKV   = OFF_CAQ    + (size_t)1024 * 1024;
constexpr size_t OFF_CAPROJ = OFF_CAKV   + (size_t)2048 * 1024;
constexpr size_t OFF_FC     = OFF_CAPROJ + (size_t)1024 * 1024;
constexpr size_t OFF_FCP    = OFF_FC     + (size_t)4096 * 1024;
constexpr size_t WTOTAL     = OFF_FCP    + (size_t)1024 * 4096;   // 16M elements

// flattened conversion grid: block ranges per job
constexpr int BLK_QKV    = 768;
constexpr int BLK_SAPROJ = 256;
constexpr int BLK_CAQ    = 256;
constexpr int BLK_CAKV   = 512;
constexpr int BLK_CAPROJ = 256;
constexpr int BLK_FC     = 1024;
constexpr int BLK_FCP    = 1024;
constexpr int BLK_MEM    = 1024;
constexpr int BLK_LN1    = 2048;
constexpr int B0 = 0;
constexpr int B1 = B0 + BLK_QKV;
constexpr int B2 = B1 + BLK_SAPROJ;
constexpr int B3 = B2 + BLK_CAQ;
constexpr int B4 = B3 + BLK_CAKV;
constexpr int B5 = B4 + BLK_CAPROJ;
constexpr int B6 = B5 + BLK_FC;
constexpr int B7 = B6 + BLK_FCP;
constexpr int B8 = B7 + BLK_MEM;
constexpr int BTOT = B8 + BLK_LN1;  // 7168

// ---------------- device scratch -------------------
__device__ float g_h[ROWS * 4096];
__device__ float g_qkv[ROWS * 3072];
__device__ float g_Qf[BH * T * HD];
__device__ float g_Qr[BH * T * HD];
__device__ float g_Kf[BH * T * HD];
__device__ float g_Kr[BH * T * HD];
__device__ float g_V [BH * T * HD];
__device__ float g_Z [BH * HD];
__device__ float g_Zpart[BH * NC * HD];
__device__ float g_Schunk[BH * NC * HD * HD];
__device__ float g_Stot[BH * HD * HD];
__device__ float g_cos[T * HD];
__device__ float g_sin[T * HD];
// tiled + swizzled bf16 operand buffers
__device__ __align__(1024) __nv_bfloat16 g_Ah[ROWS * 4096];
__device__ __align__(1024) __nv_bfloat16 g_Al[ROWS * 4096];
__device__ __align__(1024) __nv_bfloat16 g_Ah2[ROWS * 4096];
__device__ __align__(1024) __nv_bfloat16 g_Al2[ROWS * 4096];
__device__ __align__(1024) __nv_bfloat16 g_Bh[WTOTAL];
__device__ __align__(1024) __nv_bfloat16 g_Bl[WTOTAL];

// ---------------- small helpers --------------------
__device__ __forceinline__ float gelu_tanh(float x) {
    const float c = 0.7978845608028654f;
    float t = tanhf(c * (x + 0.044715f * x * x * x));
    return 0.5f * x * (1.0f + t);
}
__device__ __forceinline__ float featmap(float x) {
    return x > 0.0f ? x + 1.0f : __expf(x);
}
__device__ __forceinline__ uint32_t smem_u32(const void* p) {
    uint32_t a;
    asm("{ .reg .u64 t; cvta.to.shared.u64 t, %1; cvt.u32.u64 %0, t; }" : "=r"(a) : "l"(p));
    return a;
}
__device__ __forceinline__ uint32_t swz128(uint32_t off) {
    return off ^ ((off >> 3) & 0x70);
}
__device__ __forceinline__ void split8(const float* x, uint4& uh, uint4& ul) {
    __align__(16) __nv_bfloat16 h[8];
    __align__(16) __nv_bfloat16 l[8];
    #pragma unroll
    for (int i = 0; i < 8; i++) {
        __nv_bfloat16 hh = __float2bfloat16(x[i]);
        h[i] = hh;
        l[i] = __float2bfloat16(x[i] - __bfloat162float(hh));
    }
    uh = *(const uint4*)h;
    ul = *(const uint4*)l;
}
__device__ __forceinline__ void split2(float a, float b, uint32_t& hp, uint32_t& lp) {
    __nv_bfloat16 h0 = __float2bfloat16(a);
    __nv_bfloat16 h1 = __float2bfloat16(b);
    __nv_bfloat16 l0 = __float2bfloat16(a - __bfloat162float(h0));
    __nv_bfloat16 l1 = __float2bfloat16(b - __bfloat162float(h1));
    __nv_bfloat162 hv = {h0, h1}, lv = {l0, l1};
    hp = *(uint32_t*)&hv;
    lp = *(uint32_t*)&lv;
}

// ---------------- cp.async / ldmatrix / mma --------
__device__ __forceinline__ void cp16(uint32_t dst, const void* src) {
    asm volatile("cp.async.cg.shared.global [%0], [%1], 16;" :: "r"(dst), "l"(src));
}
__device__ __forceinline__ void cp_commit() {
    asm volatile("cp.async.commit_group;");
}
__device__ __forceinline__ void ldmx4(uint32_t& r0, uint32_t& r1, uint32_t& r2, uint32_t& r3, uint32_t addr) {
    asm volatile("ldmatrix.sync.aligned.m8n8.x4.shared.b16 {%0,%1,%2,%3}, [%4];"
                 : "=r"(r0), "=r"(r1), "=r"(r2), "=r"(r3) : "r"(addr));
}
__device__ __forceinline__ void mma16816(float* d, uint32_t a0, uint32_t a1, uint32_t a2, uint32_t a3,
                                         uint32_t b0, uint32_t b1) {
    asm volatile(
        "mma.sync.aligned.m16n8k16.row.col.f32.bf16.bf16.f32 "
        "{%0,%1,%2,%3}, {%4,%5,%6,%7}, {%8,%9}, {%0,%1,%2,%3};"
        : "+f"(d[0]), "+f"(d[1]), "+f"(d[2]), "+f"(d[3])
        : "r"(a0), "r"(a1), "r"(a2), "r"(a3), "r"(b0), "r"(b1));
}

// ---------------- RoPE tables ----------------------
__global__ void rope_init_kernel() {
    int t = blockIdx.x;
    int d = threadIdx.x;
    int i = d & 31;
    double inv = pow(10000.0, -(double)i / 32.0);
    double ang = (double)t * inv;
    g_cos[t * HD + d] = (float)cos(ang);
    g_sin[t * HD + d] = (float)sin(ang);
}

// ---------------- conversion bodies (device) --------
__device__ __forceinline__ void convW_block(
    const float* __restrict__ W, int Nn, int K,
    __nv_bfloat16* __restrict__ dsth, __nv_bfloat16* __restrict__ dstl,
    int kb, int nb, float (*smw)[65])
{
    int tid = threadIdx.x;
    #pragma unroll
    for (int i = 0; i < 4; i++) {
        int idx = tid * 4 + i;
        int kl = idx >> 4, f4 = idx & 15;
        float4 v = *(const float4*)(W + (size_t)(kb + kl) * Nn + nb + f4 * 4);
        smw[kl][f4 * 4 + 0] = v.x;
        smw[kl][f4 * 4 + 1] = v.y;
        smw[kl][f4 * 4 + 2] = v.z;
        smw[kl][f4 * 4 + 3] = v.w;
    }
    __syncthreads();
    int nkc = K >> 6, kc = kb >> 6;
    #pragma unroll
    for (int i = 0; i < 2; i++) {
        int cid = tid * 2 + i;
        int nl64 = cid >> 3, k8 = (cid & 7) * 8;
        int n = nb + nl64;
        int nt = n >> 7, nl = n & 127;
        float vals[8];
        #pragma unroll
        for (int j = 0; j < 8; j++) vals[j] = smw[k8 + j][nl64];
        uint4 uh, ul;
        split8(vals, uh, ul);
        uint32_t sw = swz128((uint32_t)(nl * 128 + k8 * 2));
        size_t tb = ((size_t)nt * nkc + kc) * TILE_BYTES + sw;
        *(uint4*)((char*)dsth + tb) = uh;
        *(uint4*)((char*)dstl + tb) = ul;
    }
}

__device__ __forceinline__ void convA_block(
    const float* __restrict__ in, int K,
    __nv_bfloat16* __restrict__ dsth, __nv_bfloat16* __restrict__ dstl,
    int blk)
{
    size_t gid = ((size_t)blk * 256 + threadIdx.x) * 8;
    int m = (int)(gid / K);
    int n0 = (int)(gid % K);
    float vals[8];
    float4 a = *(const float4*)(in + gid);
    float4 b = *(const float4*)(in + gid + 4);
    vals[0] = a.x; vals[1] = a.y; vals[2] = a.z; vals[3] = a.w;
    vals[4] = b.x; vals[5] = b.y; vals[6] = b.z; vals[7] = b.w;
    uint4 uh, ul;
    split8(vals, uh, ul);
    int nkc = K >> 6;
    int mt = m >> 7, rl = m & 127, kc = n0 >> 6, kl = n0 & 63;
    uint32_t sw = swz128((uint32_t)(rl * 128 + kl * 2));
    size_t tb = ((size_t)mt * nkc + kc) * TILE_BYTES + sw;
    *(uint4*)((char*)dsth + tb) = uh;
    *(uint4*)((char*)dstl + tb) = ul;
}

__device__ __forceinline__ void ln_block(
    const float* __restrict__ in, const float* __restrict__ gam,
    const float* __restrict__ bet, int r, float* row)
{
    int tid = threadIdx.x;
    float* red1 = row + CD;
    float* red2 = row + CD + 8;
    float* mv   = row + CD + 16;
    float4 v = ((const float4*)(in + (size_t)r * CD))[tid];
    ((float4*)row)[tid] = v;
    float s1 = v.x + v.y + v.z + v.w;
    float s2 = v.x * v.x + v.y * v.y + v.z * v.z + v.w * v.w;
    #pragma unroll
    for (int o = 16; o > 0; o >>= 1) {
        s1 += __shfl_xor_sync(0xFFFFFFFFu, s1, o);
        s2 += __shfl_xor_sync(0xFFFFFFFFu, s2, o);
    }
    if ((tid & 31) == 0) { red1[tid >> 5] = s1; red2[tid >> 5] = s2; }
    __syncthreads();
    if (tid == 0) {
        float a = 0.f, b = 0.f;
        #pragma unroll
        for (int i = 0; i < 8; i++) { a += red1[i]; b += red2[i]; }
        float mean = a * (1.0f / CD);
        mv[0] = mean;
        mv[1] = rsqrtf(b * (1.0f / CD) - mean * mean + 1e-5f);
    }
    __syncthreads();
    float mean = mv[0], rstd = mv[1];
    if (tid < 128) {
        int n0 = tid * 8;
        float vals[8];
        #pragma unroll
        for (int i = 0; i < 8; i++)
            vals[i] = (row[n0 + i] - mean) * rstd * gam[n0 + i] + bet[n0 + i];
        uint4 uh, ul;
        split8(vals, uh, ul);
        int mt = r >> 7, rl = r & 127, kc = n0 >> 6, kl = n0 & 63;
        uint32_t sw = swz128((uint32_t)(rl * 128 + kl * 2));
        size_t tb = ((size_t)(mt * 16 + kc)) * TILE_BYTES + sw;
        *(uint4*)((char*)g_Ah + tb) = uh;
        *(uint4*)((char*)g_Al + tb) = ul;
    }
}

// ---------------- standalone LN (for ln2/ln3) ------
__global__ void __launch_bounds__(256) ln_tiled_kernel(
    const float* __restrict__ in, const float* __restrict__ gam,
    const float* __restrict__ bet)
{
    __shared__ float row[CD + 32];
    ln_block(in, gam, bet, blockIdx.x, row);
}

// ---------------- ALL conversions + ln1 in one launch ----
__global__ void __launch_bounds__(256) convAll_kernel(
    const float* __restrict__ qkv_w, const float* __restrict__ saproj_w,
    const float* __restrict__ caq_w, const float* __restrict__ cakv_w,
    const float* __restrict__ caproj_w, const float* __restrict__ fc_w,
    const float* __restrict__ fcp_w, const float* __restrict__ mem,
    const float* __restrict__ x, const float* __restrict__ ln1_g,
    const float* __restrict__ ln1_b,
    __nv_bfloat16* __restrict__ Bh, __nv_bfloat16* __restrict__ Bl,
    __nv_bfloat16* __restrict__ Ah2, __nv_bfloat16* __restrict__ Al2)
{
    __shared__ float smw[64][65];
    int blk = blockIdx.x;
    if (blk < B1) {
        int lb = blk - B0;
        convW_block(qkv_w, 3072, 1024, Bh + OFF_QKV, Bl + OFF_QKV,
                    (lb % 16) * 64, (lb / 16) * 64, smw);
    } else if (blk < B2) {
        int lb = blk - B1;
        convW_block(saproj_w, 1024, 1024, Bh + OFF_SAPROJ, Bl + OFF_SAPROJ,
                    (lb % 16) * 64, (lb / 16) * 64, smw);
    } else if (blk < B3) {
        int lb = blk - B2;
        convW_block(caq_w, 1024, 1024, Bh + OFF_CAQ, Bl + OFF_CAQ,
                    (lb % 16) * 64, (lb / 16) * 64, smw);
    } else if (blk < B4) {
        int lb = blk - B3;
        convW_block(cakv_w, 2048, 1024, Bh + OFF_CAKV, Bl + OFF_CAKV,
                    (lb % 16) * 64, (lb / 16) * 64, smw);
    } else if (blk < B5) {
        int lb = blk - B4;
        convW_block(caproj_w, 1024, 1024, Bh + OFF_CAPROJ, Bl + OFF_CAPROJ,
                    (lb % 16) * 64, (lb / 16) * 64, smw);
    } else if (blk < B6) {
        int lb = blk - B5;
        convW_block(fc_w, 4096, 1024, Bh + OFF_FC, Bl + OFF_FC,
                    (lb % 16) * 64, (lb / 16) * 64, smw);
    } else if (blk < B7) {
        int lb = blk - B6;
        convW_block(fcp_w, 1024, 4096, Bh + OFF_FCP, Bl + OFF_FCP,
                    (lb % 64) * 64, (lb / 64) * 64, smw);
    } else if (blk < B8) {
        convA_block(mem, 1024, Ah2, Al2, blk - B7);
    } else {
        ln_block(x, ln1_g, ln1_b, blk - B8, &smw[0][0]);
    }
}

// ---------------- mma.sync bf16x3 GEMM (8 warps, R13 form) ----
// epi: 0 = +bias; 1 = gelu(+bias); 2 = +bias + resid;
//      3 = gelu(+bias) -> split-tiled bf16 into outAh/outAl
__global__ void __launch_bounds__(256, 1) gemm_mma_kernel(
    const __nv_bfloat16* __restrict__ Ah, const __nv_bfloat16* __restrict__ Al,
    const __nv_bfloat16* __restrict__ Bh, const __nv_bfloat16* __restrict__ Bl,
    const float* __restrict__ bias, const float* __restrict__ resid,
    float* __restrict__ out, __nv_bfloat16* __restrict__ outAh,
    __nv_bfloat16* __restrict__ outAl, int Nn, int K, int epi)
{
    extern __shared__ __align__(1024) char smg[];
    uint32_t sb = smem_u32(smg);
    int tid = threadIdx.x;
    int w = tid >> 5, l = tid & 31;
    int wm = w & 1, wn = w >> 1;           // warp tile: 64x32 at (wm*64, wn*32)
    int bx = blockIdx.x, by = blockIdx.y;
    int nkc = K >> 6;

    auto prefetch = [&](int c, int s) {
        uint32_t st = sb + s * STAGE_BYTES;
        const char* pah = (const char*)Ah + ((size_t)by * nkc + c) * TILE_BYTES;
        const char* pal = (const char*)Al + ((size_t)by * nkc + c) * TILE_BYTES;
        const char* pbh = (const char*)Bh + ((size_t)bx * nkc + c) * TILE_BYTES;
        const char* pbl = (const char*)Bl + ((size_t)bx * nkc + c) * TILE_BYTES;
        #pragma unroll
        for (int r = 0; r < 4; r++) {
            uint32_t o = (uint32_t)(r * 256 + tid) * 16;
            cp16(st + o,                  pah + o);
            cp16(st + TILE_BYTES + o,     pal + o);
            cp16(st + 2 * TILE_BYTES + o, pbh + o);
            cp16(st + 3 * TILE_BYTES + o, pbl + o);
        }
        cp_commit();
    };

    float acc[4][4][4];
    #pragma unroll
    for (int i = 0; i < 4; i++)
        #pragma unroll
        for (int j = 0; j < 4; j++)
            #pragma unroll
            for (int q = 0; q < 4; q++) acc[i][j][q] = 0.f;

    prefetch(0, 0);
    if (nkc > 1) prefetch(1, 1);

    int seg = l >> 3, l7 = l & 7;
    int arow = wm * 64 + (seg & 1) * 8 + l7;
    int akb  = (seg >> 1) * 16;
    int brow = wn * 32 + (seg >> 1) * 8 + l7;
    int bkb  = (seg & 1) * 16;

    for (int c = 0; c < nkc; c++) {
        int s = c % 3;
        if (c + 1 < nkc) asm volatile("cp.async.wait_group 1;");
        else             asm volatile("cp.async.wait_group 0;");
        __syncthreads();
        if (c + 2 < nkc) prefetch(c + 2, (c + 2) % 3);
        uint32_t st = sb + s * STAGE_BYTES;
        #pragma unroll
        for (int ks = 0; ks < 4; ks++) {
            uint32_t bh_[4][2], bl_[4][2];
            #pragma unroll
            for (int jp = 0; jp < 2; jp++) {
                uint32_t off = swz128((uint32_t)((brow + jp * 16) * 128 + ks * 32 + bkb));
                ldmx4(bh_[2 * jp][0], bh_[2 * jp][1], bh_[2 * jp + 1][0], bh_[2 * jp + 1][1],
                      st + 2 * TILE_BYTES + off);
                ldmx4(bl_[2 * jp][0], bl_[2 * jp][1], bl_[2 * jp + 1][0], bl_[2 * jp + 1][1],
                      st + 3 * TILE_BYTES + off);
            }
            #pragma unroll
            for (int i = 0; i < 4; i++) {
                uint32_t off = swz128((uint32_t)((arow + i * 16) * 128 + ks * 32 + akb));
                uint32_t a0, a1, a2, a3, c0, c1, c2, c3;
                ldmx4(a0, a1, a2, a3, st + off);
                ldmx4(c0, c1, c2, c3, st + TILE_BYTES + off);
                #pragma unroll
                for (int j = 0; j < 4; j++) {
                    mma16816(acc[i][j], a0, a1, a2, a3, bh_[j][0], bh_[j][1]);
                    mma16816(acc[i][j], a0, a1, a2, a3, bl_[j][0], bl_[j][1]);
                    mma16816(acc[i][j], c0, c1, c2, c3, bh_[j][0], bh_[j][1]);
                }
            }
        }
        __syncthreads();
    }

    // epilogue
    int g = l >> 2, tq = l & 3;
    int mBase = by * 128 + wm * 64;
    int nBase = bx * 128 + wn * 32;
    int nkcOut = Nn >> 6;
    #pragma unroll
    for (int i = 0; i < 4; i++) {
        #pragma unroll
        for (int j = 0; j < 4; j++) {
            int m0 = mBase + i * 16 + g;
            int n0 = nBase + j * 8 + tq * 2;
            float2 bb = *(const float2*)(bias + n0);
            float v0 = acc[i][j][0] + bb.x, v1 = acc[i][j][1] + bb.y;
            float v2 = acc[i][j][2] + bb.x, v3 = acc[i][j][3] + bb.y;
            if (epi == 1 || epi == 3) {
                v0 = gelu_tanh(v0); v1 = gelu_tanh(v1);
                v2 = gelu_tanh(v2); v3 = gelu_tanh(v3);
            } else if (epi == 2) {
                float2 r0 = *(const float2*)(resid + (size_t)m0 * Nn + n0);
                float2 r1 = *(const float2*)(resid + (size_t)(m0 + 8) * Nn + n0);
                v0 += r0.x; v1 += r0.y; v2 += r1.x; v3 += r1.y;
            }
            if (epi == 3) {
                int kc = n0 >> 6, kl = n0 & 63;
                uint32_t sw = swz128((uint32_t)((m0 & 127) * 128 + kl * 2));
                size_t tb0 = ((size_t)((m0 >> 7) * nkcOut + kc)) * TILE_BYTES + sw;
                uint32_t sw1 = swz128((uint32_t)(((m0 + 8) & 127) * 128 + kl * 2));
                size_t tb1 = ((size_t)(((m0 + 8) >> 7) * nkcOut + kc)) * TILE_BYTES + sw1;
                uint32_t hp, lp;
                split2(v0, v1, hp, lp);
                *(uint32_t*)((char*)outAh + tb0) = hp;
                *(uint32_t*)((char*)outAl + tb0) = lp;
                split2(v2, v3, hp, lp);
                *(uint32_t*)((char*)outAh + tb1) = hp;
                *(uint32_t*)((char*)outAl + tb1) = lp;
            } else {
                float2 o0 = {v0, v1}, o1 = {v2, v3};
                *(float2*)(out + (size_t)m0 * Nn + n0) = o0;
                *(float2*)(out + (size_t)(m0 + 8) * Nn + n0) = o1;
            }
        }
    }
}

// ---------------- feature map + RoPE ---------------
__global__ void __launch_bounds__(256) featuremap_kernel(
    const float* __restrict__ q, int qs,
    const float* __restrict__ k, int ks,
    const float* __restrict__ v, int vs)
{
    int r = blockIdx.x;
    int b = r / T, t = r % T;
    int tid = threadIdx.x;
    __shared__ float qf[CD], kf[CD];
    for (int idx = tid; idx < CD; idx += 256) {
        qf[idx] = featmap(q[(size_t)r * qs + idx]);
        kf[idx] = featmap(k[(size_t)r * ks + idx]);
    }
    __syncthreads();
    for (int idx = tid; idx < CD; idx += 256) {
        int hh = idx >> 6, d = idx & 63;
        float cs = g_cos[t * HD + d], sn = g_sin[t * HD + d];
        float qrot = (d < 32) ? -qf[hh * HD + d + 32] : qf[hh * HD + d - 32];
        float krot = (d < 32) ? -kf[hh * HD + d + 32] : kf[hh * HD + d - 32];
        size_t o = ((size_t)(b * H + hh) * T + t) * HD + d;
        float qv = qf[idx], kv = kf[idx];
        g_Qf[o] = qv;
        g_Qr[o] = qv * cs + qrot * sn;
        g_Kf[o] = kv;
        g_Kr[o] = kv * cs + krot * sn;
        g_V[o]  = v[(size_t)r * vs + idx];
    }
}

// ---------------- per-chunk Kr (outer) V sums + Kf chunk partials ----
// register-tiled: thread (ia, ja) computes S[4ia..4ia+3][4ja..4ja+3]
__global__ void __launch_bounds__(256) chunksum_kernel() {
    int bh = blockIdx.x / NC;
    int c  = blockIdx.x % NC;
    int tid = threadIdx.x;
    __shared__ float Ks[CH][HD];
    __shared__ float Vs[CH][HD];
    __shared__ float zred[4][HD];
    size_t gbase = ((size_t)bh * T + c * CH) * HD;
    for (int idx = tid; idx < CH * HD; idx += 256) {
        Ks[idx >> 6][idx & 63] = g_Kr[gbase + idx];
        Vs[idx >> 6][idx & 63] = g_V [gbase + idx];
    }
    {
        int j = tid & 63, rr = tid >> 6;
        const float* kf = g_Kf + gbase;
        float zs = 0.f;
        for (int t = rr; t < CH; t += 4) zs += kf[(size_t)t * HD + j];
        zred[rr][j] = zs;
    }
    __syncthreads();
    if (tid < 64)
        g_Zpart[(bh * NC + c) * 64 + tid] =
            zred[0][tid] + zred[1][tid] + zred[2][tid] + zred[3][tid];

    int ia = tid >> 4, ja = tid & 15;
    float acc[4][4];
    #pragma unroll
    for (int r = 0; r < 4; r++)
        #pragma unroll
        for (int q = 0; q < 4; q++) acc[r][q] = 0.f;
    for (int t = 0; t < CH; t++) {
        float4 kk = *(const float4*)&Ks[t][ia * 4];
        float4 vv = *(const float4*)&Vs[t][ja * 4];
        float kr[4] = {kk.x, kk.y, kk.z, kk.w};
        float vr[4] = {vv.x, vv.y, vv.z, vv.w};
        #pragma unroll
        for (int r = 0; r < 4; r++)
            #pragma unroll
            for (int q = 0; q < 4; q++)
                acc[r][q] = fmaf(kr[r], vr[q], acc[r][q]);
    }
    float* outp = g_Schunk + ((size_t)bh * NC + c) * (HD * HD);
    #pragma unroll
    for (int r = 0; r < 4; r++) {
        float4 o = {acc[r][0], acc[r][1], acc[r][2], acc[r][3]};
        *(float4*)&outp[(ia * 4 + r) * HD + ja * 4] = o;
    }
}

// ---------------- exclusive prefix over chunks (+ Z reduce) ----
__global__ void __launch_bounds__(256) prefix_kernel() {
    int bh = blockIdx.x;
    int e = blockIdx.y * 256 + threadIdx.x;
    if (blockIdx.y == 0 && threadIdx.x < 64) {
        int d = threadIdx.x;
        float s = 0.f;
        for (int i = 0; i < NC; i++) s += g_Zpart[(bh * NC + i) * 64 + d];
        g_Z[bh * HD + d] = s;
    }
    float run = 0.f;
    for (int c = 0; c < NC; c++) {
        size_t idx = ((size_t)bh * NC + c) * (HD * HD) + e;
        float tmp = g_Schunk[idx];
        g_Schunk[idx] = run;
        run += tmp;
    }
    g_Stot[(size_t)bh * (HD * HD) + e] = run;
}

// ---------------- write y (split-tiled bf16, K=1024 layout) ----
__device__ __forceinline__ void write_y_tiled(int row, int hh, int j, float a) {
    int rl = row & 127, mt = row >> 7;
    size_t tb = ((size_t)(mt * 16 + hh)) * TILE_BYTES + swz128((uint32_t)(rl * 128 + j * 2));
    __nv_bfloat16 hbf = __float2bfloat16(a);
    __nv_bfloat16 lbf = __float2bfloat16(a - __bfloat162float(hbf));
    *(__nv_bfloat16*)((char*)g_Ah + tb) = hbf;
    *(__nv_bfloat16*)((char*)g_Al + tb) = lbf;
}

// ---------------- causal chunked attention ----------
constexpr int SMEM_CAUSAL = (5 * HD * HD + 2 * HD) * 4;
__global__ void __launch_bounds__(256) causal_attn_kernel() {
    extern __shared__ float smc[];
    float* Qrs = smc;
    float* Krs = smc + 4096;
    float* Vs  = smc + 8192;
    float* Sps = smc + 12288;
    float* att = smc + 16384;
    float* den = smc + 20480;
    float* Zs  = smc + 20544;

    int bh = blockIdx.x / NC;
    int c  = blockIdx.x % NC;
    int b = bh / H, hh = bh % H;
    int tid = threadIdx.x;
    size_t qbase = ((size_t)bh * T + c * CH) * HD;

    for (int idx = tid; idx < 4096; idx += 256) {
        Qrs[idx] = g_Qr[qbase + idx];
        Krs[idx] = g_Kr[qbase + idx];
        Vs[idx]  = g_V [qbase + idx];
        Sps[idx] = g_Schunk[((size_t)bh * NC + c) * 4096 + idx];
    }
    if (tid < HD) Zs[tid] = g_Z[bh * HD + tid];
    __syncthreads();

    if (tid < CH) {
        const float* qf = g_Qf + qbase + (size_t)tid * HD;
        float s = 0.f;
        #pragma unroll
        for (int d = 0; d < HD; d++) s = fmaf(qf[d], Zs[d], s);
        den[tid] = s;
    }
    for (int e = tid; e < 4096; e += 256) {
        int t = e >> 6, s = e & 63;
        float v = 0.f;
        if (s <= t) {
            #pragma unroll
            for (int d = 0; d < HD; d++) v = fmaf(Qrs[t * HD + d], Krs[s * HD + d], v);
        }
        att[e] = v;
    }
    __syncthreads();

    int j = tid & 63, i0 = tid >> 6;
    #pragma unroll
    for (int k = 0; k < 16; k++) {
        int t = i0 + 4 * k;
        float a = 0.f;
        #pragma unroll
        for (int d = 0; d < HD; d++) a = fmaf(Qrs[t * HD + d], Sps[d * HD + j], a);
        #pragma unroll
        for (int s = 0; s < CH; s++) a = fmaf(att[t * HD + s], Vs[s * HD + j], a);
        a /= den[t];
        write_y_tiled(b * T + c * CH + t, hh, j, a);
    }
}

// ---------------- cross attention -------------------
__global__ void __launch_bounds__(256) cross_attn_kernel() {
    __shared__ float Qrs[4096], St[4096], den[CH], Zs[HD];
    int bh = blockIdx.x / NC;
    int c  = blockIdx.x % NC;
    int b = bh / H, hh = bh % H;
    int tid = threadIdx.x;
    size_t qbase = ((size_t)bh * T + c * CH) * HD;

    for (int idx = tid; idx < 4096; idx += 256) {
        Qrs[idx] = g_Qr[qbase + idx];
        St[idx]  = g_Stot[(size_t)bh * 4096 + idx];
    }
    if (tid < HD) Zs[tid] = g_Z[bh * HD + tid];
    __syncthreads();
    if (tid < CH) {
        const float* qf = g_Qf + qbase + (size_t)tid * HD;
        float s = 0.f;
        #pragma unroll
        for (int d = 0; d < HD; d++) s = fmaf(qf[d], Zs[d], s);
        den[tid] = s;
    }
    __syncthreads();

    int j = tid & 63, i0 = tid >> 6;
    #pragma unroll
    for (int k = 0; k < 16; k++) {
        int t = i0 + 4 * k;
        float a = 0.f;
        #pragma unroll
        for (int d = 0; d < HD; d++) a = fmaf(Qrs[t * HD + d], St[d * HD + j], a);
        a /= den[t];
        write_y_tiled(b * T + c * CH + t, hh, j, a);
    }
}

// ---------------- host ------------------------------
static void launch_gemm(const __nv_bfloat16* Ah, const __nv_bfloat16* Al,
                        const __nv_bfloat16* Bh, const __nv_bfloat16* Bl,
                        const float* bias, const float* resid, float* out,
                        __nv_bfloat16* oAh, __nv_bfloat16* oAl,
                        int Nn, int K, int epi)
{
    dim3 grid(Nn / 128, ROWS / 128);
    gemm_mma_kernel<<<grid, 256, SMEM_GEMM>>>(Ah, Al, Bh, Bl, bias, resid, out, oAh, oAl, Nn, K, epi);
}

extern "C" void kernel_launch(void* const* d_in, const int* in_sizes, int n_in,
                              void* d_out, int out_size)
{
    const float* x        = (const float*)d_in[0];
    const float* memory   = (const float*)d_in[1];
    const float* ln1_g    = (const float*)d_in[2];
    const float* ln1_b    = (const float*)d_in[3];
    const float* sa_qkv_w = (const float*)d_in[4];
    const float* sa_qkv_b = (const float*)d_in[5];
    const float* sa_proj_w= (const float*)d_in[6];
    const float* sa_proj_b= (const float*)d_in[7];
    const float* ln2_g    = (const float*)d_in[8];
    const float* ln2_b    = (const float*)d_in[9];
    const float* ca_q_w   = (const float*)d_in[10];
    const float* ca_q_b   = (const float*)d_in[11];
    const float* ca_kv_w  = (const float*)d_in[12];
    const float* ca_kv_b  = (const float*)d_in[13];
    const float* ca_proj_w= (const float*)d_in[14];
    const float* ca_proj_b= (const float*)d_in[15];
    const float* ln3_g    = (const float*)d_in[16];
    const float* ln3_b    = (const float*)d_in[17];
    const float* fc_w     = (const float*)d_in[18];
    const float* fc_b     = (const float*)d_in[19];
    const float* fcp_w    = (const float*)d_in[20];
    const float* fcp_b    = (const float*)d_in[21];
    float* out = (float*)d_out;

    cudaFuncSetAttribute(gemm_mma_kernel,
                         cudaFuncAttributeMaxDynamicSharedMemorySize, SMEM_GEMM);
    cudaFuncSetAttribute(causal_attn_kernel,
                         cudaFuncAttributeMaxDynamicSharedMemorySize, SMEM_CAUSAL);

    float *hbuf, *qkvbuf;
    __nv_bfloat16 *Ah, *Al, *Ah2, *Al2, *Bh, *Bl;
    cudaGetSymbolAddress((void**)&hbuf,   g_h);
    cudaGetSymbolAddress((void**)&qkvbuf, g_qkv);
    cudaGetSymbolAddress((void**)&Ah, g_Ah);
    cudaGetSymbolAddress((void**)&Al, g_Al);
    cudaGetSymbolAddress((void**)&Ah2, g_Ah2);
    cudaGetSymbolAddress((void**)&Al2, g_Al2);
    cudaGetSymbolAddress((void**)&Bh, g_Bh);
    cudaGetSymbolAddress((void**)&Bl, g_Bl);

    rope_init_kernel<<<T, HD>>>();

    // ---- ALL conversions + ln1 in a single launch ----
    convAll_kernel<<<BTOT, 256>>>(sa_qkv_w, sa_proj_w, ca_q_w, ca_kv_w,
                                  ca_proj_w, fc_w, fcp_w, memory,
                                  x, ln1_g, ln1_b, Bh, Bl, Ah2, Al2);

    // ---- self attention ----
    launch_gemm(Ah, Al, Bh + OFF_QKV, Bl + OFF_QKV, sa_qkv_b, nullptr, qkvbuf, nullptr, nullptr, 3072, 1024, 0);
    featuremap_kernel<<<ROWS, 256>>>(qkvbuf, 3072, qkvbuf + 1024, 3072, qkvbuf + 2048, 3072);
    chunksum_kernel<<<BH * NC, 256>>>();
    prefix_kernel<<<dim3(BH, 16), 256>>>();
    causal_attn_kernel<<<BH * NC, 256, SMEM_CAUSAL>>>();   // writes y tiles -> Ah/Al
    launch_gemm(Ah, Al, Bh + OFF_SAPROJ, Bl + OFF_SAPROJ, sa_proj_b, x, out, nullptr, nullptr, 1024, 1024, 2);

    // ---- cross attention ----
    ln_tiled_kernel<<<ROWS, 256>>>(out, ln2_g, ln2_b);
    launch_gemm(Ah, Al, Bh + OFF_CAQ, Bl + OFF_CAQ, ca_q_b, nullptr, qkvbuf, nullptr, nullptr, 1024, 1024, 0);
    launch_gemm(Ah2, Al2, Bh + OFF_CAKV, Bl + OFF_CAKV, ca_kv_b, nullptr, hbuf, nullptr, nullptr, 2048, 1024, 0);
    featuremap_kernel<<<ROWS, 256>>>(qkvbuf, 1024, hbuf, 2048, hbuf + 1024, 2048);
    chunksum_kernel<<<BH * NC, 256>>>();
    prefix_kernel<<<dim3(BH, 16), 256>>>();
    cross_attn_kernel<<<BH * NC, 256>>>();                 // writes y tiles -> Ah/Al
    launch_gemm(Ah, Al, Bh + OFF_CAPROJ, Bl + OFF_CAPROJ, ca_proj_b, out, out, nullptr, nullptr, 1024, 1024, 2);

    // ---- MLP ----
    ln_tiled_kernel<<<ROWS, 256>>>(out, ln3_g, ln3_b);
    launch_gemm(Ah, Al, Bh + OFF_FC, Bl + OFF_FC, fc_b, nullptr, nullptr, Ah2, Al2, 4096, 1024, 3);
    launch_gemm(Ah2, Al2, Bh + OFF_FCP, Bl + OFF_FCP, fcp_b, out, out, nullptr, nullptr, 1024, 4096, 2);
}

// round 17
// speedup vs baseline: 1.4287x; 1.1221x over previous
#include <cuda_runtime.h>
#include <cuda_bf16.h>
#include <math.h>
#include <stdint.h>

// ---------------- problem constants ----------------
constexpr int BATCH = 2;
constexpr int T = 1024;
constexpr int CD = 1024;      // model dim
constexpr int H = 16;
constexpr int HD = 64;
constexpr int ROWS = BATCH * T;   // 2048
constexpr int BH = BATCH * H;     // 32
constexpr int NC = 16;
constexpr int CH = 64;

// GEMM tiling: CTA 128x128 (256 threads, 8 warps, 64x32 warp tiles),
// K-chunk 64, tiles pre-swizzled in gmem, 3-stage pipe
constexpr int TILE_BYTES = 128 * 64 * 2;                 // 16384
constexpr int STAGE_BYTES = 4 * TILE_BYTES;              // 65536
constexpr int SMEM_GEMM = 3 * STAGE_BYTES;               // 196608

// per-weight tile-buffer offsets (elements)
constexpr size_t OFF_QKV    = 0;
constexpr size_t OFF_SAPROJ = OFF_QKV    + (size_t)3072 * 1024;
constexpr size_t OFF_CAQ    = OFF_SAPROJ + (size_t)1024 * 1024;
constexpr size_t OFF_CAKV   = OFF_CAQ    + (size_t)1024 * 1024;
constexpr size_t OFF_CAPROJ = OFF_CAKV   + (size_t)2048 * 1024;
constexpr size_t OFF_FC     = OFF_CAPROJ + (size_t)1024 * 1024;
constexpr size_t OFF_FCP    = OFF_FC     + (size_t)4096 * 1024;
constexpr size_t WTOTAL     = OFF_FCP    + (size_t)1024 * 4096;   // 16M elements

// flattened conversion grid: block ranges per job
constexpr int BLK_QKV    = 768;
constexpr int BLK_SAPROJ = 256;
constexpr int BLK_CAQ    = 256;
constexpr int BLK_CAKV   = 512;
constexpr int BLK_CAPROJ = 256;
constexpr int BLK_FC     = 1024;
constexpr int BLK_FCP    = 1024;
constexpr int BLK_MEM    = 1024;
constexpr int BLK_LN1    = 2048;
constexpr int B0 = 0;
constexpr int B1 = B0 + BLK_QKV;
constexpr int B2 = B1 + BLK_SAPROJ;
constexpr int B3 = B2 + BLK_CAQ;
constexpr int B4 = B3 + BLK_CAKV;
constexpr int B5 = B4 + BLK_CAPROJ;
constexpr int B6 = B5 + BLK_FC;
constexpr int B7 = B6 + BLK_FCP;
constexpr int B8 = B7 + BLK_MEM;
constexpr int BTOT = B8 + BLK_LN1;  // 7168

// ---------------- device scratch -------------------
__device__ float g_h[ROWS * 4096];
__device__ float g_qkv[ROWS * 3072];
__device__ float g_Qf[BH * T * HD];
__device__ float g_Qr[BH * T * HD];
__device__ float g_Kf[BH * T * HD];
__device__ float g_Kr[BH * T * HD];
__device__ float g_V [BH * T * HD];
__device__ float g_Z [BH * HD];
__device__ float g_Zpart[BH * NC * HD];
__device__ float g_Schunk[BH * NC * HD * HD];
__device__ float g_Stot[BH * HD * HD];
__device__ float g_cos[T * HD];
__device__ float g_sin[T * HD];
// tiled + swizzled bf16 operand buffers
__device__ __align__(1024) __nv_bfloat16 g_Ah[ROWS * 4096];
__device__ __align__(1024) __nv_bfloat16 g_Al[ROWS * 4096];
__device__ __align__(1024) __nv_bfloat16 g_Ah2[ROWS * 4096];
__device__ __align__(1024) __nv_bfloat16 g_Al2[ROWS * 4096];
__device__ __align__(1024) __nv_bfloat16 g_Bh[WTOTAL];
__device__ __align__(1024) __nv_bfloat16 g_Bl[WTOTAL];

// ---------------- small helpers --------------------
__device__ __forceinline__ float gelu_tanh(float x) {
    const float c = 0.7978845608028654f;
    float t = tanhf(c * (x + 0.044715f * x * x * x));
    return 0.5f * x * (1.0f + t);
}
__device__ __forceinline__ float featmap(float x) {
    return x > 0.0f ? x + 1.0f : __expf(x);
}
__device__ __forceinline__ uint32_t smem_u32(const void* p) {
    uint32_t a;
    asm("{ .reg .u64 t; cvta.to.shared.u64 t, %1; cvt.u32.u64 %0, t; }" : "=r"(a) : "l"(p));
    return a;
}
__device__ __forceinline__ uint32_t swz128(uint32_t off) {
    return off ^ ((off >> 3) & 0x70);
}
__device__ __forceinline__ void split8(const float* x, uint4& uh, uint4& ul) {
    __align__(16) __nv_bfloat16 h[8];
    __align__(16) __nv_bfloat16 l[8];
    #pragma unroll
    for (int i = 0; i < 8; i++) {
        __nv_bfloat16 hh = __float2bfloat16(x[i]);
        h[i] = hh;
        l[i] = __float2bfloat16(x[i] - __bfloat162float(hh));
    }
    uh = *(const uint4*)h;
    ul = *(const uint4*)l;
}
__device__ __forceinline__ void split2(float a, float b, uint32_t& hp, uint32_t& lp) {
    __nv_bfloat16 h0 = __float2bfloat16(a);
    __nv_bfloat16 h1 = __float2bfloat16(b);
    __nv_bfloat16 l0 = __float2bfloat16(a - __bfloat162float(h0));
    __nv_bfloat16 l1 = __float2bfloat16(b - __bfloat162float(h1));
    __nv_bfloat162 hv = {h0, h1}, lv = {l0, l1};
    hp = *(uint32_t*)&hv;
    lp = *(uint32_t*)&lv;
}

// ---------------- cp.async / ldmatrix / mma --------
__device__ __forceinline__ void cp16(uint32_t dst, const void* src) {
    asm volatile("cp.async.cg.shared.global [%0], [%1], 16;" :: "r"(dst), "l"(src));
}
__device__ __forceinline__ void cp_commit() {
    asm volatile("cp.async.commit_group;");
}
__device__ __forceinline__ void ldmx4(uint32_t& r0, uint32_t& r1, uint32_t& r2, uint32_t& r3, uint32_t addr) {
    asm volatile("ldmatrix.sync.aligned.m8n8.x4.shared.b16 {%0,%1,%2,%3}, [%4];"
                 : "=r"(r0), "=r"(r1), "=r"(r2), "=r"(r3) : "r"(addr));
}
__device__ __forceinline__ void mma16816(float* d, uint32_t a0, uint32_t a1, uint32_t a2, uint32_t a3,
                                         uint32_t b0, uint32_t b1) {
    asm volatile(
        "mma.sync.aligned.m16n8k16.row.col.f32.bf16.bf16.f32 "
        "{%0,%1,%2,%3}, {%4,%5,%6,%7}, {%8,%9}, {%0,%1,%2,%3};"
        : "+f"(d[0]), "+f"(d[1]), "+f"(d[2]), "+f"(d[3])
        : "r"(a0), "r"(a1), "r"(a2), "r"(a3), "r"(b0), "r"(b1));
}

// ---------------- RoPE tables ----------------------
__global__ void rope_init_kernel() {
    int t = blockIdx.x;
    int d = threadIdx.x;
    int i = d & 31;
    double inv = pow(10000.0, -(double)i / 32.0);
    double ang = (double)t * inv;
    g_cos[t * HD + d] = (float)cos(ang);
    g_sin[t * HD + d] = (float)sin(ang);
}

// ---------------- conversion bodies (device) --------
__device__ __forceinline__ void convW_block(
    const float* __restrict__ W, int Nn, int K,
    __nv_bfloat16* __restrict__ dsth, __nv_bfloat16* __restrict__ dstl,
    int kb, int nb, float (*smw)[65])
{
    int tid = threadIdx.x;
    #pragma unroll
    for (int i = 0; i < 4; i++) {
        int idx = tid * 4 + i;
        int kl = idx >> 4, f4 = idx & 15;
        float4 v = *(const float4*)(W + (size_t)(kb + kl) * Nn + nb + f4 * 4);
        smw[kl][f4 * 4 + 0] = v.x;
        smw[kl][f4 * 4 + 1] = v.y;
        smw[kl][f4 * 4 + 2] = v.z;
        smw[kl][f4 * 4 + 3] = v.w;
    }
    __syncthreads();
    int nkc = K >> 6, kc = kb >> 6;
    #pragma unroll
    for (int i = 0; i < 2; i++) {
        int cid = tid * 2 + i;
        int nl64 = cid >> 3, k8 = (cid & 7) * 8;
        int n = nb + nl64;
        int nt = n >> 7, nl = n & 127;
        float vals[8];
        #pragma unroll
        for (int j = 0; j < 8; j++) vals[j] = smw[k8 + j][nl64];
        uint4 uh, ul;
        split8(vals, uh, ul);
        uint32_t sw = swz128((uint32_t)(nl * 128 + k8 * 2));
        size_t tb = ((size_t)nt * nkc + kc) * TILE_BYTES + sw;
        *(uint4*)((char*)dsth + tb) = uh;
        *(uint4*)((char*)dstl + tb) = ul;
    }
}

__device__ __forceinline__ void convA_block(
    const float* __restrict__ in, int K,
    __nv_bfloat16* __restrict__ dsth, __nv_bfloat16* __restrict__ dstl,
    int blk)
{
    size_t gid = ((size_t)blk * 256 + threadIdx.x) * 8;
    int m = (int)(gid / K);
    int n0 = (int)(gid % K);
    float vals[8];
    float4 a = *(const float4*)(in + gid);
    float4 b = *(const float4*)(in + gid + 4);
    vals[0] = a.x; vals[1] = a.y; vals[2] = a.z; vals[3] = a.w;
    vals[4] = b.x; vals[5] = b.y; vals[6] = b.z; vals[7] = b.w;
    uint4 uh, ul;
    split8(vals, uh, ul);
    int nkc = K >> 6;
    int mt = m >> 7, rl = m & 127, kc = n0 >> 6, kl = n0 & 63;
    uint32_t sw = swz128((uint32_t)(rl * 128 + kl * 2));
    size_t tb = ((size_t)mt * nkc + kc) * TILE_BYTES + sw;
    *(uint4*)((char*)dsth + tb) = uh;
    *(uint4*)((char*)dstl + tb) = ul;
}

__device__ __forceinline__ void ln_block(
    const float* __restrict__ in, const float* __restrict__ gam,
    const float* __restrict__ bet, int r, float* row)
{
    int tid = threadIdx.x;
    float* red1 = row + CD;
    float* red2 = row + CD + 8;
    float* mv   = row + CD + 16;
    float4 v = ((const float4*)(in + (size_t)r * CD))[tid];
    ((float4*)row)[tid] = v;
    float s1 = v.x + v.y + v.z + v.w;
    float s2 = v.x * v.x + v.y * v.y + v.z * v.z + v.w * v.w;
    #pragma unroll
    for (int o = 16; o > 0; o >>= 1) {
        s1 += __shfl_xor_sync(0xFFFFFFFFu, s1, o);
        s2 += __shfl_xor_sync(0xFFFFFFFFu, s2, o);
    }
    if ((tid & 31) == 0) { red1[tid >> 5] = s1; red2[tid >> 5] = s2; }
    __syncthreads();
    if (tid == 0) {
        float a = 0.f, b = 0.f;
        #pragma unroll
        for (int i = 0; i < 8; i++) { a += red1[i]; b += red2[i]; }
        float mean = a * (1.0f / CD);
        mv[0] = mean;
        mv[1] = rsqrtf(b * (1.0f / CD) - mean * mean + 1e-5f);
    }
    __syncthreads();
    float mean = mv[0], rstd = mv[1];
    if (tid < 128) {
        int n0 = tid * 8;
        float vals[8];
        #pragma unroll
        for (int i = 0; i < 8; i++)
            vals[i] = (row[n0 + i] - mean) * rstd * gam[n0 + i] + bet[n0 + i];
        uint4 uh, ul;
        split8(vals, uh, ul);
        int mt = r >> 7, rl = r & 127, kc = n0 >> 6, kl = n0 & 63;
        uint32_t sw = swz128((uint32_t)(rl * 128 + kl * 2));
        size_t tb = ((size_t)(mt * 16 + kc)) * TILE_BYTES + sw;
        *(uint4*)((char*)g_Ah + tb) = uh;
        *(uint4*)((char*)g_Al + tb) = ul;
    }
}

// ---------------- standalone LN (for ln2/ln3) ------
__global__ void __launch_bounds__(256) ln_tiled_kernel(
    const float* __restrict__ in, const float* __restrict__ gam,
    const float* __restrict__ bet)
{
    __shared__ float row[CD + 32];
    ln_block(in, gam, bet, blockIdx.x, row);
}

// ---------------- ALL conversions + ln1 in one launch ----
__global__ void __launch_bounds__(256) convAll_kernel(
    const float* __restrict__ qkv_w, const float* __restrict__ saproj_w,
    const float* __restrict__ caq_w, const float* __restrict__ cakv_w,
    const float* __restrict__ caproj_w, const float* __restrict__ fc_w,
    const float* __restrict__ fcp_w, const float* __restrict__ mem,
    const float* __restrict__ x, const float* __restrict__ ln1_g,
    const float* __restrict__ ln1_b,
    __nv_bfloat16* __restrict__ Bh, __nv_bfloat16* __restrict__ Bl,
    __nv_bfloat16* __restrict__ Ah2, __nv_bfloat16* __restrict__ Al2)
{
    __shared__ float smw[64][65];
    int blk = blockIdx.x;
    if (blk < B1) {
        int lb = blk - B0;
        convW_block(qkv_w, 3072, 1024, Bh + OFF_QKV, Bl + OFF_QKV,
                    (lb % 16) * 64, (lb / 16) * 64, smw);
    } else if (blk < B2) {
        int lb = blk - B1;
        convW_block(saproj_w, 1024, 1024, Bh + OFF_SAPROJ, Bl + OFF_SAPROJ,
                    (lb % 16) * 64, (lb / 16) * 64, smw);
    } else if (blk < B3) {
        int lb = blk - B2;
        convW_block(caq_w, 1024, 1024, Bh + OFF_CAQ, Bl + OFF_CAQ,
                    (lb % 16) * 64, (lb / 16) * 64, smw);
    } else if (blk < B4) {
        int lb = blk - B3;
        convW_block(cakv_w, 2048, 1024, Bh + OFF_CAKV, Bl + OFF_CAKV,
                    (lb % 16) * 64, (lb / 16) * 64, smw);
    } else if (blk < B5) {
        int lb = blk - B4;
        convW_block(caproj_w, 1024, 1024, Bh + OFF_CAPROJ, Bl + OFF_CAPROJ,
                    (lb % 16) * 64, (lb / 16) * 64, smw);
    } else if (blk < B6) {
        int lb = blk - B5;
        convW_block(fc_w, 4096, 1024, Bh + OFF_FC, Bl + OFF_FC,
                    (lb % 16) * 64, (lb / 16) * 64, smw);
    } else if (blk < B7) {
        int lb = blk - B6;
        convW_block(fcp_w, 1024, 4096, Bh + OFF_FCP, Bl + OFF_FCP,
                    (lb % 64) * 64, (lb / 64) * 64, smw);
    } else if (blk < B8) {
        convA_block(mem, 1024, Ah2, Al2, blk - B7);
    } else {
        ln_block(x, ln1_g, ln1_b, blk - B8, &smw[0][0]);
    }
}

// ---------------- mma.sync bf16x3 GEMM (8 warps) ----
// epi: 0 = +bias; 1 = gelu(+bias); 2 = +bias + resid;
//      3 = gelu(+bias) -> split-tiled bf16 into outAh/outAl
__global__ void __launch_bounds__(256, 1) gemm_mma_kernel(
    const __nv_bfloat16* __restrict__ Ah, const __nv_bfloat16* __restrict__ Al,
    const __nv_bfloat16* __restrict__ Bh, const __nv_bfloat16* __restrict__ Bl,
    const float* __restrict__ bias, const float* __restrict__ resid,
    float* __restrict__ out, __nv_bfloat16* __restrict__ outAh,
    __nv_bfloat16* __restrict__ outAl, int Nn, int K, int epi)
{
    extern __shared__ __align__(1024) char smg[];
    uint32_t sb = smem_u32(smg);
    int tid = threadIdx.x;
    int w = tid >> 5, l = tid & 31;
    int wm = w & 1, wn = w >> 1;           // warp tile: 64x32 at (wm*64, wn*32)
    int bx = blockIdx.x, by = blockIdx.y;
    int nkc = K >> 6;

    auto prefetch = [&](int c, int s) {
        uint32_t st = sb + s * STAGE_BYTES;
        const char* pah = (const char*)Ah + ((size_t)by * nkc + c) * TILE_BYTES;
        const char* pal = (const char*)Al + ((size_t)by * nkc + c) * TILE_BYTES;
        const char* pbh = (const char*)Bh + ((size_t)bx * nkc + c) * TILE_BYTES;
        const char* pbl = (const char*)Bl + ((size_t)bx * nkc + c) * TILE_BYTES;
        #pragma unroll
        for (int r = 0; r < 4; r++) {
            uint32_t o = (uint32_t)(r * 256 + tid) * 16;
            cp16(st + o,                  pah + o);
            cp16(st + TILE_BYTES + o,     pal + o);
            cp16(st + 2 * TILE_BYTES + o, pbh + o);
            cp16(st + 3 * TILE_BYTES + o, pbl + o);
        }
        cp_commit();
    };

    float acc[4][4][4];
    #pragma unroll
    for (int i = 0; i < 4; i++)
        #pragma unroll
        for (int j = 0; j < 4; j++)
            #pragma unroll
            for (int q = 0; q < 4; q++) acc[i][j][q] = 0.f;

    prefetch(0, 0);
    if (nkc > 1) prefetch(1, 1);

    int seg = l >> 3, l7 = l & 7;
    int arow = wm * 64 + (seg & 1) * 8 + l7;
    int akb  = (seg >> 1) * 16;
    int brow = wn * 32 + (seg >> 1) * 8 + l7;
    int bkb  = (seg & 1) * 16;

    for (int c = 0; c < nkc; c++) {
        int s = c % 3;
        if (c + 1 < nkc) asm volatile("cp.async.wait_group 1;");
        else             asm volatile("cp.async.wait_group 0;");
        __syncthreads();
        if (c + 2 < nkc) prefetch(c + 2, (c + 2) % 3);
        uint32_t st = sb + s * STAGE_BYTES;
        #pragma unroll
        for (int ks = 0; ks < 4; ks++) {
            uint32_t bh_[4][2], bl_[4][2];
            #pragma unroll
            for (int jp = 0; jp < 2; jp++) {
                uint32_t off = swz128((uint32_t)((brow + jp * 16) * 128 + ks * 32 + bkb));
                ldmx4(bh_[2 * jp][0], bh_[2 * jp][1], bh_[2 * jp + 1][0], bh_[2 * jp + 1][1],
                      st + 2 * TILE_BYTES + off);
                ldmx4(bl_[2 * jp][0], bl_[2 * jp][1], bl_[2 * jp + 1][0], bl_[2 * jp + 1][1],
                      st + 3 * TILE_BYTES + off);
            }
            #pragma unroll
            for (int i = 0; i < 4; i++) {
                uint32_t off = swz128((uint32_t)((arow + i * 16) * 128 + ks * 32 + akb));
                uint32_t a0, a1, a2, a3, c0, c1, c2, c3;
                ldmx4(a0, a1, a2, a3, st + off);
                ldmx4(c0, c1, c2, c3, st + TILE_BYTES + off);
                #pragma unroll
                for (int j = 0; j < 4; j++) {
                    mma16816(acc[i][j], a0, a1, a2, a3, bh_[j][0], bh_[j][1]);
                    mma16816(acc[i][j], a0, a1, a2, a3, bl_[j][0], bl_[j][1]);
                    mma16816(acc[i][j], c0, c1, c2, c3, bh_[j][0], bh_[j][1]);
                }
            }
        }
        __syncthreads();
    }

    // epilogue
    int g = l >> 2, tq = l & 3;
    int mBase = by * 128 + wm * 64;
    int nBase = bx * 128 + wn * 32;
    int nkcOut = Nn >> 6;
    #pragma unroll
    for (int i = 0; i < 4; i++) {
        #pragma unroll
        for (int j = 0; j < 4; j++) {
            int m0 = mBase + i * 16 + g;
            int n0 = nBase + j * 8 + tq * 2;
            float2 bb = *(const float2*)(bias + n0);
            float v0 = acc[i][j][0] + bb.x, v1 = acc[i][j][1] + bb.y;
            float v2 = acc[i][j][2] + bb.x, v3 = acc[i][j][3] + bb.y;
            if (epi == 1 || epi == 3) {
                v0 = gelu_tanh(v0); v1 = gelu_tanh(v1);
                v2 = gelu_tanh(v2); v3 = gelu_tanh(v3);
            } else if (epi == 2) {
                float2 r0 = *(const float2*)(resid + (size_t)m0 * Nn + n0);
                float2 r1 = *(const float2*)(resid + (size_t)(m0 + 8) * Nn + n0);
                v0 += r0.x; v1 += r0.y; v2 += r1.x; v3 += r1.y;
            }
            if (epi == 3) {
                int kc = n0 >> 6, kl = n0 & 63;
                uint32_t sw = swz128((uint32_t)((m0 & 127) * 128 + kl * 2));
                size_t tb0 = ((size_t)((m0 >> 7) * nkcOut + kc)) * TILE_BYTES + sw;
                uint32_t sw1 = swz128((uint32_t)(((m0 + 8) & 127) * 128 + kl * 2));
                size_t tb1 = ((size_t)(((m0 + 8) >> 7) * nkcOut + kc)) * TILE_BYTES + sw1;
                uint32_t hp, lp;
                split2(v0, v1, hp, lp);
                *(uint32_t*)((char*)outAh + tb0) = hp;
                *(uint32_t*)((char*)outAl + tb0) = lp;
                split2(v2, v3, hp, lp);
                *(uint32_t*)((char*)outAh + tb1) = hp;
                *(uint32_t*)((char*)outAl + tb1) = lp;
            } else {
                float2 o0 = {v0, v1}, o1 = {v2, v3};
                *(float2*)(out + (size_t)m0 * Nn + n0) = o0;
                *(float2*)(out + (size_t)(m0 + 8) * Nn + n0) = o1;
            }
        }
    }
}

// ---------------- feature map + RoPE ---------------
__global__ void __launch_bounds__(256) featuremap_kernel(
    const float* __restrict__ q, int qs,
    const float* __restrict__ k, int ks,
    const float* __restrict__ v, int vs)
{
    int r = blockIdx.x;
    int b = r / T, t = r % T;
    int tid = threadIdx.x;
    __shared__ float qf[CD], kf[CD];
    for (int idx = tid; idx < CD; idx += 256) {
        qf[idx] = featmap(q[(size_t)r * qs + idx]);
        kf[idx] = featmap(k[(size_t)r * ks + idx]);
    }
    __syncthreads();
    for (int idx = tid; idx < CD; idx += 256) {
        int hh = idx >> 6, d = idx & 63;
        float cs = g_cos[t * HD + d], sn = g_sin[t * HD + d];
        float qrot = (d < 32) ? -qf[hh * HD + d + 32] : qf[hh * HD + d - 32];
        float krot = (d < 32) ? -kf[hh * HD + d + 32] : kf[hh * HD + d - 32];
        size_t o = ((size_t)(b * H + hh) * T + t) * HD + d;
        float qv = qf[idx], kv = kf[idx];
        g_Qf[o] = qv;
        g_Qr[o] = qv * cs + qrot * sn;
        g_Kf[o] = kv;
        g_Kr[o] = kv * cs + krot * sn;
        g_V[o]  = v[(size_t)r * vs + idx];
    }
}

// ---------------- per-chunk Kr (outer) V sums + Kf chunk partials ----
__global__ void __launch_bounds__(256) chunksum_kernel() {
    int bh = blockIdx.x / NC;
    int c  = blockIdx.x % NC;
    int tid = threadIdx.x;
    __shared__ float Ks[CH][HD];
    __shared__ float Vs[CH][HD];
    __shared__ float zred[4][HD];
    size_t gbase = ((size_t)bh * T + c * CH) * HD;
    for (int idx = tid; idx < CH * HD; idx += 256) {
        Ks[idx >> 6][idx & 63] = g_Kr[gbase + idx];
        Vs[idx >> 6][idx & 63] = g_V [gbase + idx];
    }
    {
        int j = tid & 63, rr = tid >> 6;
        const float* kf = g_Kf + gbase;
        float zs = 0.f;
        for (int t = rr; t < CH; t += 4) zs += kf[(size_t)t * HD + j];
        zred[rr][j] = zs;
    }
    __syncthreads();
    if (tid < 64)
        g_Zpart[(bh * NC + c) * 64 + tid] =
            zred[0][tid] + zred[1][tid] + zred[2][tid] + zred[3][tid];

    int ia = tid >> 4, ja = tid & 15;
    float acc[4][4];
    #pragma unroll
    for (int r = 0; r < 4; r++)
        #pragma unroll
        for (int q = 0; q < 4; q++) acc[r][q] = 0.f;
    for (int t = 0; t < CH; t++) {
        float4 kk = *(const float4*)&Ks[t][ia * 4];
        float4 vv = *(const float4*)&Vs[t][ja * 4];
        float kr[4] = {kk.x, kk.y, kk.z, kk.w};
        float vr[4] = {vv.x, vv.y, vv.z, vv.w};
        #pragma unroll
        for (int r = 0; r < 4; r++)
            #pragma unroll
            for (int q = 0; q < 4; q++)
                acc[r][q] = fmaf(kr[r], vr[q], acc[r][q]);
    }
    float* outp = g_Schunk + ((size_t)bh * NC + c) * (HD * HD);
    #pragma unroll
    for (int r = 0; r < 4; r++) {
        float4 o = {acc[r][0], acc[r][1], acc[r][2], acc[r][3]};
        *(float4*)&outp[(ia * 4 + r) * HD + ja * 4] = o;
    }
}

// ---------------- exclusive prefix over chunks (+ Z reduce) ----
__global__ void __launch_bounds__(256) prefix_kernel() {
    int bh = blockIdx.x;
    int e = blockIdx.y * 256 + threadIdx.x;
    if (blockIdx.y == 0 && threadIdx.x < 64) {
        int d = threadIdx.x;
        float s = 0.f;
        for (int i = 0; i < NC; i++) s += g_Zpart[(bh * NC + i) * 64 + d];
        g_Z[bh * HD + d] = s;
    }
    float run = 0.f;
    for (int c = 0; c < NC; c++) {
        size_t idx = ((size_t)bh * NC + c) * (HD * HD) + e;
        float tmp = g_Schunk[idx];
        g_Schunk[idx] = run;
        run += tmp;
    }
    g_Stot[(size_t)bh * (HD * HD) + e] = run;
}

// ---------------- write y (split-tiled bf16, K=1024 layout) ----
__device__ __forceinline__ void write_y_tiled(int row, int hh, int j, float a) {
    int rl = row & 127, mt = row >> 7;
    size_t tb = ((size_t)(mt * 16 + hh)) * TILE_BYTES + swz128((uint32_t)(rl * 128 + j * 2));
    __nv_bfloat16 hbf = __float2bfloat16(a);
    __nv_bfloat16 lbf = __float2bfloat16(a - __bfloat162float(hbf));
    *(__nv_bfloat16*)((char*)g_Ah + tb) = hbf;
    *(__nv_bfloat16*)((char*)g_Al + tb) = lbf;
}

// ---------------- causal chunked attention (register-tiled) ----
// smem floats: Qrs 0..4095 | KrT 4096..8447 (64x68) | Vs 8448..12543
//              Sps 12544..16639 | att 16640..20735 | den 20736 | Zs 20800
constexpr int SMEM_CAUSAL = 20864 * 4;
__global__ void __launch_bounds__(256) causal_attn_kernel() {
    extern __shared__ float smc[];
    float* Qrs = smc;
    float* KrT = smc + 4096;     // [d][t], stride 68
    float* Vs  = smc + 8448;     // [s][j]
    float* Sps = smc + 12544;    // [d][j]
    float* att = smc + 16640;    // [t][s]
    float* den = smc + 20736;
    float* Zs  = smc + 20800;

    int bh = blockIdx.x / NC;
    int c  = blockIdx.x % NC;
    int b = bh / H, hh = bh % H;
    int tid = threadIdx.x;
    size_t qbase = ((size_t)bh * T + c * CH) * HD;

    for (int idx = tid; idx < 4096; idx += 256) {
        int t = idx >> 6, d = idx & 63;
        Qrs[idx] = g_Qr[qbase + idx];
        KrT[d * 68 + t] = g_Kr[qbase + idx];
        Vs[idx]  = g_V [qbase + idx];
        Sps[idx] = g_Schunk[((size_t)bh * NC + c) * 4096 + idx];
    }
    if (tid < HD) Zs[tid] = g_Z[bh * HD + tid];
    __syncthreads();

    if (tid < CH) {
        const float* qf = g_Qf + qbase + (size_t)tid * HD;
        float s = 0.f;
        #pragma unroll
        for (int d = 0; d < HD; d++) s = fmaf(qf[d], Zs[d], s);
        den[tid] = s;
    }
    // att tile: thread (ta, sa) -> att[4ta..4ta+3][4sa..4sa+3]
    {
        int ta = tid >> 4, sa = tid & 15;
        float acc[4][4];
        #pragma unroll
        for (int r = 0; r < 4; r++)
            #pragma unroll
            for (int q = 0; q < 4; q++) acc[r][q] = 0.f;
        for (int d = 0; d < HD; d++) {
            float4 kf = *(const float4*)&KrT[d * 68 + sa * 4];
            float kr[4] = {kf.x, kf.y, kf.z, kf.w};
            float qr[4];
            #pragma unroll
            for (int r = 0; r < 4; r++) qr[r] = Qrs[(ta * 4 + r) * 64 + d];
            #pragma unroll
            for (int r = 0; r < 4; r++)
                #pragma unroll
                for (int q = 0; q < 4; q++)
                    acc[r][q] = fmaf(qr[r], kr[q], acc[r][q]);
        }
        #pragma unroll
        for (int r = 0; r < 4; r++) {
            int t = ta * 4 + r;
            float4 o;
            o.x = (sa * 4 + 0 <= t) ? acc[r][0] : 0.f;
            o.y = (sa * 4 + 1 <= t) ? acc[r][1] : 0.f;
            o.z = (sa * 4 + 2 <= t) ? acc[r][2] : 0.f;
            o.w = (sa * 4 + 3 <= t) ? acc[r][3] : 0.f;
            *(float4*)&att[t * 64 + sa * 4] = o;
        }
    }
    __syncthreads();

    // y tile: thread (ta, ja) -> y[4ta..4ta+3][4ja..4ja+3]
    {
        int ta = tid >> 4, ja = tid & 15;
        float a2[4][4];
        #pragma unroll
        for (int r = 0; r < 4; r++)
            #pragma unroll
            for (int q = 0; q < 4; q++) a2[r][q] = 0.f;
        for (int d = 0; d < HD; d++) {
            float4 s4 = *(const float4*)&Sps[d * 64 + ja * 4];
            float sr[4] = {s4.x, s4.y, s4.z, s4.w};
            float qr[4];
            #pragma unroll
            for (int r = 0; r < 4; r++) qr[r] = Qrs[(ta * 4 + r) * 64 + d];
            #pragma unroll
            for (int r = 0; r < 4; r++)
                #pragma unroll
                for (int q = 0; q < 4; q++)
                    a2[r][q] = fmaf(qr[r], sr[q], a2[r][q]);
        }
        for (int s = 0; s < CH; s++) {
            float4 v4 = *(const float4*)&Vs[s * 64 + ja * 4];
            float vr[4] = {v4.x, v4.y, v4.z, v4.w};
            float ar[4];
            #pragma unroll
            for (int r = 0; r < 4; r++) ar[r] = att[(ta * 4 + r) * 64 + s];
            #pragma unroll
            for (int r = 0; r < 4; r++)
                #pragma unroll
                for (int q = 0; q < 4; q++)
                    a2[r][q] = fmaf(ar[r], vr[q], a2[r][q]);
        }
        #pragma unroll
        for (int r = 0; r < 4; r++) {
            int t = ta * 4 + r;
            float dv = den[t];
            int row = b * T + c * CH + t;
            #pragma unroll
            for (int q = 0; q < 4; q++)
                write_y_tiled(row, hh, ja * 4 + q, a2[r][q] / dv);
        }
    }
}

// ---------------- cross attention (register-tiled) ----
__global__ void __launch_bounds__(256) cross_attn_kernel() {
    __shared__ float Qrs[4096], St[4096], den[CH], Zs[HD];
    int bh = blockIdx.x / NC;
    int c  = blockIdx.x % NC;
    int b = bh / H, hh = bh % H;
    int tid = threadIdx.x;
    size_t qbase = ((size_t)bh * T + c * CH) * HD;

    for (int idx = tid; idx < 4096; idx += 256) {
        Qrs[idx] = g_Qr[qbase + idx];
        St[idx]  = g_Stot[(size_t)bh * 4096 + idx];
    }
    if (tid < HD) Zs[tid] = g_Z[bh * HD + tid];
    __syncthreads();
    if (tid < CH) {
        const float* qf = g_Qf + qbase + (size_t)tid * HD;
        float s = 0.f;
        #pragma unroll
        for (int d = 0; d < HD; d++) s = fmaf(qf[d], Zs[d], s);
        den[tid] = s;
    }
    __syncthreads();

    int ta = tid >> 4, ja = tid & 15;
    float a2[4][4];
    #pragma unroll
    for (int r = 0; r < 4; r++)
        #pragma unroll
        for (int q = 0; q < 4; q++) a2[r][q] = 0.f;
    for (int d = 0; d < HD; d++) {
        float4 s4 = *(const float4*)&St[d * 64 + ja * 4];
        float sr[4] = {s4.x, s4.y, s4.z, s4.w};
        float qr[4];
        #pragma unroll
        for (int r = 0; r < 4; r++) qr[r] = Qrs[(ta * 4 + r) * 64 + d];
        #pragma unroll
        for (int r = 0; r < 4; r++)
            #pragma unroll
            for (int q = 0; q < 4; q++)
                a2[r][q] = fmaf(qr[r], sr[q], a2[r][q]);
    }
    #pragma unroll
    for (int r = 0; r < 4; r++) {
        int t = ta * 4 + r;
        float dv = den[t];
        int row = b * T + c * CH + t;
        #pragma unroll
        for (int q = 0; q < 4; q++)
            write_y_tiled(row, hh, ja * 4 + q, a2[r][q] / dv);
    }
}

// ---------------- host ------------------------------
static void launch_gemm(const __nv_bfloat16* Ah, const __nv_bfloat16* Al,
                        const __nv_bfloat16* Bh, const __nv_bfloat16* Bl,
                        const float* bias, const float* resid, float* out,
                        __nv_bfloat16* oAh, __nv_bfloat16* oAl,
                        int Nn, int K, int epi)
{
    dim3 grid(Nn / 128, ROWS / 128);
    gemm_mma_kernel<<<grid, 256, SMEM_GEMM>>>(Ah, Al, Bh, Bl, bias, resid, out, oAh, oAl, Nn, K, epi);
}

extern "C" void kernel_launch(void* const* d_in, const int* in_sizes, int n_in,
                              void* d_out, int out_size)
{
    const float* x        = (const float*)d_in[0];
    const float* memory   = (const float*)d_in[1];
    const float* ln1_g    = (const float*)d_in[2];
    const float* ln1_b    = (const float*)d_in[3];
    const float* sa_qkv_w = (const float*)d_in[4];
    const float* sa_qkv_b = (const float*)d_in[5];
    const float* sa_proj_w= (const float*)d_in[6];
    const float* sa_proj_b= (const float*)d_in[7];
    const float* ln2_g    = (const float*)d_in[8];
    const float* ln2_b    = (const float*)d_in[9];
    const float* ca_q_w   = (const float*)d_in[10];
    const float* ca_q_b   = (const float*)d_in[11];
    const float* ca_kv_w  = (const float*)d_in[12];
    const float* ca_kv_b  = (const float*)d_in[13];
    const float* ca_proj_w= (const float*)d_in[14];
    const float* ca_proj_b= (const float*)d_in[15];
    const float* ln3_g    = (const float*)d_in[16];
    const float* ln3_b    = (const float*)d_in[17];
    const float* fc_w     = (const float*)d_in[18];
    const float* fc_b     = (const float*)d_in[19];
    const float* fcp_w    = (const float*)d_in[20];
    const float* fcp_b    = (const float*)d_in[21];
    float* out = (float*)d_out;

    cudaFuncSetAttribute(gemm_mma_kernel,
                         cudaFuncAttributeMaxDynamicSharedMemorySize, SMEM_GEMM);
    cudaFuncSetAttribute(causal_attn_kernel,
                         cudaFuncAttributeMaxDynamicSharedMemorySize, SMEM_CAUSAL);

    float *hbuf, *qkvbuf;
    __nv_bfloat16 *Ah, *Al, *Ah2, *Al2, *Bh, *Bl;
    cudaGetSymbolAddress((void**)&hbuf,   g_h);
    cudaGetSymbolAddress((void**)&qkvbuf, g_qkv);
    cudaGetSymbolAddress((void**)&Ah, g_Ah);
    cudaGetSymbolAddress((void**)&Al, g_Al);
    cudaGetSymbolAddress((void**)&Ah2, g_Ah2);
    cudaGetSymbolAddress((void**)&Al2, g_Al2);
    cudaGetSymbolAddress((void**)&Bh, g_Bh);
    cudaGetSymbolAddress((void**)&Bl, g_Bl);

    rope_init_kernel<<<T, HD>>>();

    // ---- ALL conversions + ln1 in a single launch ----
    convAll_kernel<<<BTOT, 256>>>(sa_qkv_w, sa_proj_w, ca_q_w, ca_kv_w,
                                  ca_proj_w, fc_w, fcp_w, memory,
                                  x, ln1_g, ln1_b, Bh, Bl, Ah2, Al2);

    // ---- self attention ----
    launch_gemm(Ah, Al, Bh + OFF_QKV, Bl + OFF_QKV, sa_qkv_b, nullptr, qkvbuf, nullptr, nullptr, 3072, 1024, 0);
    featuremap_kernel<<<ROWS, 256>>>(qkvbuf, 3072, qkvbuf + 1024, 3072, qkvbuf + 2048, 3072);
    chunksum_kernel<<<BH * NC, 256>>>();
    prefix_kernel<<<dim3(BH, 16), 256>>>();
    causal_attn_kernel<<<BH * NC, 256, SMEM_CAUSAL>>>();   // writes y tiles -> Ah/Al
    launch_gemm(Ah, Al, Bh + OFF_SAPROJ, Bl + OFF_SAPROJ, sa_proj_b, x, out, nullptr, nullptr, 1024, 1024, 2);

    // ---- cross attention ----
    ln_tiled_kernel<<<ROWS, 256>>>(out, ln2_g, ln2_b);
    launch_gemm(Ah, Al, Bh + OFF_CAQ, Bl + OFF_CAQ, ca_q_b, nullptr, qkvbuf, nullptr, nullptr, 1024, 1024, 0);
    launch_gemm(Ah2, Al2, Bh + OFF_CAKV, Bl + OFF_CAKV, ca_kv_b, nullptr, hbuf, nullptr, nullptr, 2048, 1024, 0);
    featuremap_kernel<<<ROWS, 256>>>(qkvbuf, 1024, hbuf, 2048, hbuf + 1024, 2048);
    chunksum_kernel<<<BH * NC, 256>>>();
    prefix_kernel<<<dim3(BH, 16), 256>>>();
    cross_attn_kernel<<<BH * NC, 256>>>();                 // writes y tiles -> Ah/Al
    launch_gemm(Ah, Al, Bh + OFF_CAPROJ, Bl + OFF_CAPROJ, ca_proj_b, out, out, nullptr, nullptr, 1024, 1024, 2);

    // ---- MLP ----
    ln_tiled_kernel<<<ROWS, 256>>>(out, ln3_g, ln3_b);
    launch_gemm(Ah, Al, Bh + OFF_FC, Bl + OFF_FC, fc_b, nullptr, nullptr, Ah2, Al2, 4096, 1024, 3);
    launch_gemm(Ah2, Al2, Bh + OFF_FCP, Bl + OFF_FCP, fcp_b, out, out, nullptr, nullptr, 1024, 4096, 2);
}